// round 7
// baseline (speedup 1.0000x reference)
#include <cuda_runtime.h>
#include <cstdint>
#include <math.h>
#include <mma.h>

using namespace nvcuda;

// Problem constants
#define BB   8
#define TT   2048
#define ROWS (BB * TT)      // 16384
#define DIN  64
#define DM   256
#define DI   512
#define NST  16
#define RR   16
#define DOUT 128
#define DBCN 48             // R + 2N
#define LAY  2

// ---------------------------------------------------------------------------
// Scratch (static device globals)
// ---------------------------------------------------------------------------
__device__ float g_h   [ROWS * DM];
__device__ float g_xz  [ROWS * 2 * DI];
__device__ float g_xc  [ROWS * DI];
__device__ float g_dbc [ROWS * DBCN];
__device__ float g_dbc2[ROWS * DBCN];     // split-K partial
__device__ float g_y   [ROWS * DI];
__device__ float g_part[BB * 32 * DM];
// tf32-truncated copies of GEMM B-operands (+x)
#define W_IN_OFF  0
#define WIN_OFF   (W_IN_OFF + DIN * DM)
#define WX_OFF    (WIN_OFF + LAY * DM * 2 * DI)
#define WOUT_OFF  (WX_OFF + LAY * DI * DBCN)
#define WT_TOTAL  (WOUT_OFF + LAY * DI * DM)
__device__ float g_wt [WT_TOTAL];
__device__ float g_xtf[ROWS * DIN];

// ---------------------------------------------------------------------------
// tf32 truncation kernels
// ---------------------------------------------------------------------------
struct CvtJob  { const float* src; float* dst; int n; };
struct CvtJobs { CvtJob j[4]; };

__global__ void tf32_cvt_multi(CvtJobs jobs, int total)
{
    int i = blockIdx.x * blockDim.x + threadIdx.x;
    if (i >= total) return;
#pragma unroll
    for (int k = 0; k < 4; k++) {
        if (i < jobs.j[k].n) {
            jobs.j[k].dst[i] = wmma::__float_to_tf32(jobs.j[k].src[i]);
            return;
        }
        i -= jobs.j[k].n;
    }
}

__global__ void tf32_cvt(const float* __restrict__ src, float* __restrict__ dst, int n)
{
    int i = blockIdx.x * blockDim.x + threadIdx.x;
    if (i < n) dst[i] = wmma::__float_to_tf32(src[i]);
}

// ---------------------------------------------------------------------------
// cp.async helpers
// ---------------------------------------------------------------------------
__device__ __forceinline__ void cp16(unsigned int smem_addr, const float* gptr)
{
    asm volatile("cp.async.cg.shared.global [%0], [%1], 16;\n"
                 :: "r"(smem_addr), "l"(gptr));
}
__device__ __forceinline__ void cp_commit()
{
    asm volatile("cp.async.commit_group;\n");
}
template<int N>
__device__ __forceinline__ void cp_wait()
{
    asm volatile("cp.async.wait_group %0;\n" :: "n"(N));
}

// ---------------------------------------------------------------------------
// TF32 tensor-core GEMM, 4-stage cp.async pipeline.
// Supports split-K via blockIdx.z: A += z*aZoff, B += z*bZoff, C += z*cZoff.
// lda = row stride of A (may exceed K for split-K).
// ---------------------------------------------------------------------------
template<int BN, int WM>
__global__ __launch_bounds__(256, 2) void tgemm(
    const float* __restrict__ A, const float* __restrict__ B,
    const float* __restrict__ bias, float* __restrict__ C,
    int M, int N, int K, int lda,
    size_t aZoff, size_t bZoff, size_t cZoff, int trunc_out)
{
    constexpr int BM = 128, BK = 16, STAGES = 4;
    constexpr int LDA = BK + 4;
    constexpr int LDB = BN + 4;
    constexpr int ASZ = BM * LDA;
    constexpr int BSZ = BK * LDB;
    constexpr int WNW = 8 / WM;
    constexpr int AM  = BM / (WM * 16);
    constexpr int NF  = BN / (WNW * 16);
    constexpr int NB4 = BN / 4;
    constexpr int BCH = BK * BN / 4;

    extern __shared__ float smem[];
    float* As = smem;
    float* Bs = smem + STAGES * ASZ;

    A += (size_t)blockIdx.z * aZoff;
    B += (size_t)blockIdx.z * bZoff;
    C += (size_t)blockIdx.z * cZoff;

    const int tid  = threadIdx.x;
    const int lane = tid & 31;
    const int wid  = tid >> 5;
    const int wm   = wid % WM;
    const int wn   = wid / WM;
    const int brow = blockIdx.y * BM;
    const int bcol = blockIdx.x * BN;

    wmma::fragment<wmma::accumulator, 16, 16, 8, float> acc[AM][NF];
#pragma unroll
    for (int i = 0; i < AM; i++)
#pragma unroll
        for (int j = 0; j < NF; j++)
            wmma::fill_fragment(acc[i][j], 0.f);

    const int ar0 = tid >> 2;
    const int ar1 = (tid + 256) >> 2;
    const int ac  = (tid & 3) * 4;

    auto loadStage = [&](int st, int k0) {
        unsigned int abase = (unsigned int)__cvta_generic_to_shared(As + st * ASZ);
        cp16(abase + (unsigned int)(ar0 * LDA + ac) * 4,
             &A[(size_t)(brow + ar0) * lda + k0 + ac]);
        cp16(abase + (unsigned int)(ar1 * LDA + ac) * 4,
             &A[(size_t)(brow + ar1) * lda + k0 + ac]);
        unsigned int bbase = (unsigned int)__cvta_generic_to_shared(Bs + st * BSZ);
#pragma unroll
        for (int u = 0; u < (BCH + 255) / 256; u++) {
            int i = tid + 256 * u;
            if ((BCH % 256 == 0) || (i < BCH)) {
                int r = i / NB4, c = (i % NB4) * 4;
                cp16(bbase + (unsigned int)(r * LDB + c) * 4,
                     &B[(size_t)(k0 + r) * N + bcol + c]);
            }
        }
    };

    const int ktiles = K / BK;

#pragma unroll
    for (int s = 0; s < STAGES - 1; s++) {
        if (s < ktiles) loadStage(s, s * BK);
        cp_commit();
    }

    for (int it = 0; it < ktiles; it++) {
        cp_wait<STAGES - 2>();
        __syncthreads();

        const int st = it % STAGES;
        const float* a0 = As + st * ASZ;
        const float* b0 = Bs + st * BSZ;
#pragma unroll
        for (int kk = 0; kk < BK; kk += 8) {
            wmma::fragment<wmma::matrix_a, 16, 16, 8, wmma::precision::tf32,
                           wmma::row_major> af[AM];
            wmma::fragment<wmma::matrix_b, 16, 16, 8, wmma::precision::tf32,
                           wmma::row_major> bf[NF];
#pragma unroll
            for (int i = 0; i < AM; i++)
                wmma::load_matrix_sync(af[i],
                    a0 + (wm * AM * 16 + i * 16) * LDA + kk, LDA);
#pragma unroll
            for (int j = 0; j < NF; j++)
                wmma::load_matrix_sync(bf[j],
                    b0 + kk * LDB + wn * NF * 16 + j * 16, LDB);
#pragma unroll
            for (int i = 0; i < AM; i++)
#pragma unroll
                for (int j = 0; j < NF; j++)
                    wmma::mma_sync(acc[i][j], af[i], bf[j], acc[i][j]);
        }

        const int nf = it + STAGES - 1;
        if (nf < ktiles) loadStage(nf % STAGES, nf * BK);
        cp_commit();
    }

    cp_wait<0>();
    __syncthreads();

    float* Ep = smem + wid * 256;
    const int er = lane >> 1;
    const int ec = (lane & 1) * 8;
#pragma unroll
    for (int i = 0; i < AM; i++) {
#pragma unroll
        for (int j = 0; j < NF; j++) {
            wmma::store_matrix_sync(Ep, acc[i][j], 16, wmma::mem_row_major);
            __syncwarp();
            int gr = brow + wm * AM * 16 + i * 16 + er;
            int gc = bcol + wn * NF * 16 + j * 16 + ec;
            float v[8];
#pragma unroll
            for (int q = 0; q < 8; q++) {
                float t = Ep[er * 16 + ec + q] + (bias ? bias[gc + q] : 0.f);
                v[q] = trunc_out ? wmma::__float_to_tf32(t) : t;
            }
            *(float4*)&C[(size_t)gr * N + gc]     = make_float4(v[0], v[1], v[2], v[3]);
            *(float4*)&C[(size_t)gr * N + gc + 4] = make_float4(v[4], v[5], v[6], v[7]);
            __syncwarp();
        }
    }
}

// ---------------------------------------------------------------------------
// Depthwise causal conv (K=4) + SiLU, float4-vectorized over d.
// ---------------------------------------------------------------------------
__global__ void conv_silu_v4(const float* __restrict__ cw,
                             const float* __restrict__ cb)
{
    int idx = blockIdx.x * blockDim.x + threadIdx.x;   // ROWS * DI/4
    if (idx >= ROWS * (DI / 4)) return;
    int dv  = idx & (DI / 4 - 1);     // 0..127, d = dv*4
    int row = idx >> 7;
    int t   = row & (TT - 1);
    int d   = dv * 4;

    const float* xi = g_xz + (size_t)row * (2 * DI) + d;
    float4 x0 = *(const float4*)xi;
    float4 x1 = (t >= 1) ? *(const float4*)(xi - 2 * DI) : make_float4(0, 0, 0, 0);
    float4 x2 = (t >= 2) ? *(const float4*)(xi - 4 * DI) : make_float4(0, 0, 0, 0);
    float4 x3 = (t >= 3) ? *(const float4*)(xi - 6 * DI) : make_float4(0, 0, 0, 0);

    // per-d weights: cw[(d+i)*4 + k]
    float4 wa = *(const float4*)&cw[(d + 0) * 4];
    float4 wb = *(const float4*)&cw[(d + 1) * 4];
    float4 wc = *(const float4*)&cw[(d + 2) * 4];
    float4 wd = *(const float4*)&cw[(d + 3) * 4];
    float4 bc = *(const float4*)&cb[d];

    float4 acc;
    acc.x = bc.x + wa.w * x0.x + wa.z * x1.x + wa.y * x2.x + wa.x * x3.x;
    acc.y = bc.y + wb.w * x0.y + wb.z * x1.y + wb.y * x2.y + wb.x * x3.y;
    acc.z = bc.z + wc.w * x0.z + wc.z * x1.z + wc.y * x2.z + wc.x * x3.z;
    acc.w = bc.w + wd.w * x0.w + wd.z * x1.w + wd.y * x2.w + wd.x * x3.w;

    float4 o;
    o.x = wmma::__float_to_tf32(__fdividef(acc.x, 1.f + __expf(-acc.x)));
    o.y = wmma::__float_to_tf32(__fdividef(acc.y, 1.f + __expf(-acc.y)));
    o.z = wmma::__float_to_tf32(__fdividef(acc.z, 1.f + __expf(-acc.z)));
    o.w = wmma::__float_to_tf32(__fdividef(acc.w, 1.f + __expf(-acc.w)));
    *(float4*)&g_xc[(size_t)row * DI + d] = o;
}

// ---------------------------------------------------------------------------
// Selective scan fused with dt-softplus AND gating.
// dbc is the sum of two split-K partials (g_dbc + g_dbc2), summed at load.
// ---------------------------------------------------------------------------
#define SCH 16
__global__ __launch_bounds__(128) void ssm_scan_fused(
    const float* __restrict__ A_log_l, const float* __restrict__ Dp_l,
    const float* __restrict__ Wdt_l,   const float* __restrict__ bdt_l)
{
    __shared__ __align__(16) float s_dt[2][SCH][32];
    __shared__ __align__(16) float s_x [2][SCH][32];
    __shared__ __align__(16) float s_z [2][SCH][32];
    __shared__ __align__(16) float s_db[2][SCH][52];
    __shared__ float s_wdt[16][33];

    const int b   = blockIdx.x >> 4;
    const int dg  = blockIdx.x & 15;
    const int d0  = dg * 32;
    const int tid = threadIdx.x;
    const int q   = tid & 3;
    const int dl  = tid >> 2;
    const int d   = d0 + dl;

    const int tl  = tid >> 3;
    const int seg = tid & 7;

    const int r0 = tid / 12,         c0 = tid % 12;
    const int r1 = (tid + 128) / 12, c1 = (tid + 128) % 12;
    const bool ld1 = (tid < 64);

    for (int i = tid; i < 16 * 32; i += 128)
        s_wdt[i >> 5][i & 31] = Wdt_l[(i >> 5) * DI + d0 + (i & 31)];
    float bdt4[4];
#pragma unroll
    for (int j = 0; j < 4; j++)
        bdt4[j] = bdt_l[d0 + seg * 4 + j];

    float a[4];
#pragma unroll
    for (int j = 0; j < 4; j++)
        a[j] = -__expf(A_log_l[d * NST + q * 4 + j]);
    const float dp = Dp_l[d];

    const size_t rb = (size_t)b * TT;

    float h0 = 0.f, h1 = 0.f, h2 = 0.f, h3 = 0.f;

    auto loadDb = [&](size_t rowg, int c) -> float4 {
        float4 p0 = *(const float4*)&g_dbc [rowg * DBCN + c * 4];
        float4 p1 = *(const float4*)&g_dbc2[rowg * DBCN + c * 4];
        return make_float4(p0.x + p1.x, p0.y + p1.y, p0.z + p1.z, p0.w + p1.w);
    };

    auto computeDt = [&](int bf) {
        float a0 = bdt4[0], a1 = bdt4[1], a2 = bdt4[2], a3 = bdt4[3];
#pragma unroll
        for (int r = 0; r < 16; r++) {
            float dbv = s_db[bf][tl][r];
            a0 += dbv * s_wdt[r][seg * 4 + 0];
            a1 += dbv * s_wdt[r][seg * 4 + 1];
            a2 += dbv * s_wdt[r][seg * 4 + 2];
            a3 += dbv * s_wdt[r][seg * 4 + 3];
        }
        s_dt[bf][tl][seg * 4 + 0] = (a0 > 20.f) ? a0 : log1pf(__expf(a0));
        s_dt[bf][tl][seg * 4 + 1] = (a1 > 20.f) ? a1 : log1pf(__expf(a1));
        s_dt[bf][tl][seg * 4 + 2] = (a2 > 20.f) ? a2 : log1pf(__expf(a2));
        s_dt[bf][tl][seg * 4 + 3] = (a3 > 20.f) ? a3 : log1pf(__expf(a3));
    };

    {
        size_t row = rb + tl;
        *(float4*)&s_x [0][tl][seg * 4] = *(const float4*)&g_xc[row * DI + d0 + seg * 4];
        *(float4*)&s_z [0][tl][seg * 4] = *(const float4*)&g_xz[row * (2 * DI) + DI + d0 + seg * 4];
        *(float4*)&s_db[0][r0][c0 * 4]  = loadDb(rb + r0, c0);
        if (ld1)
            *(float4*)&s_db[0][r1][c1 * 4] = loadDb(rb + r1, c1);
    }
    __syncthreads();
    computeDt(0);
    __syncthreads();

    int buf = 0;
    const int NC = TT / SCH;
    for (int c = 0; c < NC; c++) {
        float4 vx, vz, vdb0, vdb1;
        const bool more = (c + 1 < NC);
        if (more) {
            size_t cro = rb + (size_t)(c + 1) * SCH;
            size_t row = cro + tl;
            vx   = *(const float4*)&g_xc[row * DI + d0 + seg * 4];
            vz   = *(const float4*)&g_xz[row * (2 * DI) + DI + d0 + seg * 4];
            vdb0 = loadDb(cro + r0, c0);
            if (ld1) vdb1 = loadDb(cro + r1, c1);
        }

#pragma unroll
        for (int it = 0; it < SCH; it++) {
            float dt  = s_dt[buf][it][dl];
            float x   = s_x [buf][it][dl];
            float4 Bv = *(const float4*)&s_db[buf][it][RR + q * 4];
            float4 Cv = *(const float4*)&s_db[buf][it][RR + NST + q * 4];
            float z   = s_z [buf][it][dl];

            float dtx = dt * x;
            h0 = __expf(dt * a[0]) * h0 + dtx * Bv.x;
            h1 = __expf(dt * a[1]) * h1 + dtx * Bv.y;
            h2 = __expf(dt * a[2]) * h2 + dtx * Bv.z;
            h3 = __expf(dt * a[3]) * h3 + dtx * Bv.w;

            float pv = h0 * Cv.x + h1 * Cv.y + h2 * Cv.z + h3 * Cv.w;
            pv += __shfl_xor_sync(0xffffffffu, pv, 1);
            pv += __shfl_xor_sync(0xffffffffu, pv, 2);

            if (q == 0) {
                float sz = __fdividef(z, 1.f + __expf(-z));
                size_t row = rb + (size_t)c * SCH + it;
                g_y[row * DI + d] = wmma::__float_to_tf32((pv + dp * x) * sz);
            }
        }

        if (more) {
            *(float4*)&s_x [buf ^ 1][tl][seg * 4] = vx;
            *(float4*)&s_z [buf ^ 1][tl][seg * 4] = vz;
            *(float4*)&s_db[buf ^ 1][r0][c0 * 4]  = vdb0;
            if (ld1)
                *(float4*)&s_db[buf ^ 1][r1][c1 * 4] = vdb1;
            __syncthreads();
            computeDt(buf ^ 1);
            __syncthreads();
        }
        buf ^= 1;
    }
}

// ---------------------------------------------------------------------------
// Mean over T (two-stage) + out-projection
// ---------------------------------------------------------------------------
__global__ void mean_part()
{
    int b = blockIdx.x >> 5;
    int c = blockIdx.x & 31;
    int col = threadIdx.x;

    const float* hp = g_h + ((size_t)b * TT + (size_t)c * 64) * DM + col;
    float s = 0.f;
#pragma unroll 8
    for (int t = 0; t < 64; t++)
        s += hp[(size_t)t * DM];
    g_part[(b * 32 + c) * DM + col] = s;
}

__global__ void mean_proj2(const float* __restrict__ Wop,
                           const float* __restrict__ bop,
                           float* __restrict__ out)
{
    __shared__ float hm[DM];
    int b = blockIdx.x;
    int c = threadIdx.x;

    float s = 0.f;
#pragma unroll
    for (int i = 0; i < 32; i++)
        s += g_part[(b * 32 + i) * DM + c];
    hm[c] = s * (1.f / (float)TT);
    __syncthreads();

    if (c < DOUT) {
        float acc = bop[c];
#pragma unroll 4
        for (int k = 0; k < DM; k++)
            acc += hm[k] * Wop[k * DOUT + c];
        out[b * DOUT + c] = acc;
    }
}

// ---------------------------------------------------------------------------
// Orchestration
// ---------------------------------------------------------------------------
static constexpr int SMEM_T(int BN)
{
    return 4 * (128 * 20 + 16 * (BN + 4)) * 4;
}

extern "C" void kernel_launch(void* const* d_in, const int* in_sizes, int n_in,
                              void* d_out, int out_size)
{
    const float* x        = (const float*)d_in[0];
    const float* W_in     = (const float*)d_in[1];
    const float* b_in     = (const float*)d_in[2];
    const float* Win      = (const float*)d_in[3];
    const float* bin_     = (const float*)d_in[4];
    const float* conv_w   = (const float*)d_in[5];
    const float* conv_b   = (const float*)d_in[6];
    const float* Wx       = (const float*)d_in[7];
    const float* Wdt      = (const float*)d_in[8];
    const float* bdt      = (const float*)d_in[9];
    const float* A_log    = (const float*)d_in[10];
    const float* Dp       = (const float*)d_in[11];
    const float* Wout     = (const float*)d_in[12];
    const float* W_op     = (const float*)d_in[13];
    const float* b_op     = (const float*)d_in[14];
    float* out = (float*)d_out;

    float *hbuf, *xzbuf, *xcbuf, *dbcbuf, *dbc2buf, *ybuf, *wt, *xtf;
    cudaGetSymbolAddress((void**)&hbuf,    g_h);
    cudaGetSymbolAddress((void**)&xzbuf,   g_xz);
    cudaGetSymbolAddress((void**)&xcbuf,   g_xc);
    cudaGetSymbolAddress((void**)&dbcbuf,  g_dbc);
    cudaGetSymbolAddress((void**)&dbc2buf, g_dbc2);
    cudaGetSymbolAddress((void**)&ybuf,    g_y);
    cudaGetSymbolAddress((void**)&wt,      g_wt);
    cudaGetSymbolAddress((void**)&xtf,     g_xtf);

    constexpr int SM128 = SMEM_T(128);
    constexpr int SM48  = SMEM_T(48);
    cudaFuncSetAttribute(tgemm<128, 4>, cudaFuncAttributeMaxDynamicSharedMemorySize, SM128);
    cudaFuncSetAttribute(tgemm<48, 8>,  cudaFuncAttributeMaxDynamicSharedMemorySize, SM48);

    // launch 1: truncate weights
    {
        CvtJobs jobs;
        jobs.j[0] = { W_in, wt + W_IN_OFF, DIN * DM          };
        jobs.j[1] = { Win,  wt + WIN_OFF,  LAY * DM * 2 * DI };
        jobs.j[2] = { Wx,   wt + WX_OFF,   LAY * DI * DBCN   };
        jobs.j[3] = { Wout, wt + WOUT_OFF, LAY * DI * DM     };
        int total = 0;
        for (int k = 0; k < 4; k++) total += jobs.j[k].n;
        tf32_cvt_multi<<<(total + 255) / 256, 256>>>(jobs, total);
    }
    // launch 2: truncate x
    tf32_cvt<<<(ROWS * DIN + 255) / 256, 256>>>(x, xtf, ROWS * DIN);

    // launch 3: in_proj
    {
        dim3 g(DM / 128, ROWS / 128, 1);
        tgemm<128, 4><<<g, 256, SM128>>>(xtf, wt + W_IN_OFF, b_in, hbuf,
                                         ROWS, DM, DIN, DIN, 0, 0, 0, 1);
    }

    const int CONV_BLOCKS = (ROWS * (DI / 4) + 255) / 256;

    for (int l = 0; l < LAY; l++) {
        const float* Win_l  = wt + WIN_OFF  + (size_t)l * DM * 2 * DI;
        const float* bin_l  = bin_   + (size_t)l * 2 * DI;
        const float* cw_l   = conv_w + (size_t)l * DI * 4;
        const float* cb_l   = conv_b + (size_t)l * DI;
        const float* Wx_l   = wt + WX_OFF   + (size_t)l * DI * DBCN;
        const float* Wdt_l  = Wdt    + (size_t)l * RR * DI;
        const float* bdt_l  = bdt    + (size_t)l * DI;
        const float* Alog_l = A_log  + (size_t)l * DI * NST;
        const float* Dp_l   = Dp     + (size_t)l * DI;
        const float* Wout_l = wt + WOUT_OFF + (size_t)l * DI * DM;

        // launch 4 (l=0): xz GEMM -> profiled slot
        {
            dim3 g((2 * DI) / 128, ROWS / 128, 1);
            tgemm<128, 4><<<g, 256, SM128>>>(hbuf, Win_l, bin_l, xzbuf,
                                             ROWS, 2 * DI, DM, DM, 0, 0, 0, 0);
        }
        // conv
        conv_silu_v4<<<CONV_BLOCKS, 256>>>(cw_l, cb_l);
        // dbc = xc @ Wx, split-K=2 (z=0 -> g_dbc, z=1 -> g_dbc2)
        {
            dim3 g(1, ROWS / 128, 2);
            tgemm<48, 8><<<g, 256, SM48>>>(
                xcbuf, Wx_l, nullptr, dbcbuf,
                ROWS, DBCN, DI / 2, DI,
                (size_t)(DI / 2),                 // A: advance K/2 cols
                (size_t)(DI / 2) * DBCN,          // B: advance K/2 rows
                (size_t)(dbc2buf - dbcbuf),       // C: second partial buffer
                0);
        }
        // scan (+dt +gating)
        ssm_scan_fused<<<BB * (DI / 32), 128>>>(Alog_l, Dp_l, Wdt_l, bdt_l);
        // h = y @ Wout
        {
            dim3 g(DM / 128, ROWS / 128, 1);
            tgemm<128, 4><<<g, 256, SM128>>>(ybuf, Wout_l, nullptr, hbuf,
                                             ROWS, DM, DI, DI, 0, 0, 0, 1);
        }
    }

    mean_part<<<BB * 32, DM>>>();
    mean_proj2<<<BB, DM>>>(W_op, b_op, out);
}

// round 8
// speedup vs baseline: 1.6749x; 1.6749x over previous
#include <cuda_runtime.h>
#include <cstdint>
#include <math.h>
#include <mma.h>

using namespace nvcuda;

// Problem constants
#define BB   8
#define TT   2048
#define ROWS (BB * TT)      // 16384
#define DIN  64
#define DM   256
#define DI   512
#define NST  16
#define RR   16
#define DOUT 128
#define DBCN 48             // R + 2N
#define LAY  2
// parallel scan split
#define GG   8              // time groups
#define TG   (TT / GG)      // 256 steps per group
#define SCH  16             // steps per smem chunk

// ---------------------------------------------------------------------------
// Scratch (static device globals)
// ---------------------------------------------------------------------------
__device__ float g_h   [ROWS * DM];
__device__ float g_xz  [ROWS * 2 * DI];
__device__ float g_xc  [ROWS * DI];
__device__ float g_dbc [ROWS * DBCN];
__device__ float g_y   [ROWS * DI];
__device__ float g_part[BB * 32 * DM];
// parallel-scan intermediates: 128 (b,dg) x G groups x (16 states x 32 lanes)
__device__ float g_hend[BB * 16 * GG * 512];
__device__ float g_hin [BB * 16 * GG * 512];
__device__ float g_sdt [BB * 16 * GG * 32];
// tf32-truncated copies of GEMM B-operands (+x)
#define W_IN_OFF  0
#define WIN_OFF   (W_IN_OFF + DIN * DM)
#define WX_OFF    (WIN_OFF + LAY * DM * 2 * DI)
#define WOUT_OFF  (WX_OFF + LAY * DI * DBCN)
#define WT_TOTAL  (WOUT_OFF + LAY * DI * DM)
__device__ float g_wt [WT_TOTAL];
__device__ float g_xtf[ROWS * DIN];

// ---------------------------------------------------------------------------
// tf32 truncation kernels
// ---------------------------------------------------------------------------
struct CvtJob  { const float* src; float* dst; int n; };
struct CvtJobs { CvtJob j[4]; };

__global__ void tf32_cvt_multi(CvtJobs jobs, int total)
{
    int i = blockIdx.x * blockDim.x + threadIdx.x;
    if (i >= total) return;
#pragma unroll
    for (int k = 0; k < 4; k++) {
        if (i < jobs.j[k].n) {
            jobs.j[k].dst[i] = wmma::__float_to_tf32(jobs.j[k].src[i]);
            return;
        }
        i -= jobs.j[k].n;
    }
}

__global__ void tf32_cvt(const float* __restrict__ src, float* __restrict__ dst, int n)
{
    int i = blockIdx.x * blockDim.x + threadIdx.x;
    if (i < n) dst[i] = wmma::__float_to_tf32(src[i]);
}

// ---------------------------------------------------------------------------
// cp.async helpers
// ---------------------------------------------------------------------------
__device__ __forceinline__ void cp16(unsigned int smem_addr, const float* gptr)
{
    asm volatile("cp.async.cg.shared.global [%0], [%1], 16;\n"
                 :: "r"(smem_addr), "l"(gptr));
}
__device__ __forceinline__ void cp_commit()
{
    asm volatile("cp.async.commit_group;\n");
}
template<int N>
__device__ __forceinline__ void cp_wait()
{
    asm volatile("cp.async.wait_group %0;\n" :: "n"(N));
}

// ---------------------------------------------------------------------------
// TF32 tensor-core GEMM, 4-stage cp.async pipeline.
// ---------------------------------------------------------------------------
template<int BN, int WM>
__global__ __launch_bounds__(256, 2) void tgemm(
    const float* __restrict__ A, const float* __restrict__ B,
    const float* __restrict__ bias, float* __restrict__ C,
    int M, int N, int K, int trunc_out)
{
    constexpr int BM = 128, BK = 16, STAGES = 4;
    constexpr int LDA = BK + 4;
    constexpr int LDB = BN + 4;
    constexpr int ASZ = BM * LDA;
    constexpr int BSZ = BK * LDB;
    constexpr int WNW = 8 / WM;
    constexpr int AM  = BM / (WM * 16);
    constexpr int NF  = BN / (WNW * 16);
    constexpr int NB4 = BN / 4;
    constexpr int BCH = BK * BN / 4;

    extern __shared__ float smem[];
    float* As = smem;
    float* Bs = smem + STAGES * ASZ;

    const int tid  = threadIdx.x;
    const int lane = tid & 31;
    const int wid  = tid >> 5;
    const int wm   = wid % WM;
    const int wn   = wid / WM;
    const int brow = blockIdx.y * BM;
    const int bcol = blockIdx.x * BN;

    wmma::fragment<wmma::accumulator, 16, 16, 8, float> acc[AM][NF];
#pragma unroll
    for (int i = 0; i < AM; i++)
#pragma unroll
        for (int j = 0; j < NF; j++)
            wmma::fill_fragment(acc[i][j], 0.f);

    const int ar0 = tid >> 2;
    const int ar1 = (tid + 256) >> 2;
    const int ac  = (tid & 3) * 4;

    auto loadStage = [&](int st, int k0) {
        unsigned int abase = (unsigned int)__cvta_generic_to_shared(As + st * ASZ);
        cp16(abase + (unsigned int)(ar0 * LDA + ac) * 4,
             &A[(size_t)(brow + ar0) * K + k0 + ac]);
        cp16(abase + (unsigned int)(ar1 * LDA + ac) * 4,
             &A[(size_t)(brow + ar1) * K + k0 + ac]);
        unsigned int bbase = (unsigned int)__cvta_generic_to_shared(Bs + st * BSZ);
#pragma unroll
        for (int u = 0; u < (BCH + 255) / 256; u++) {
            int i = tid + 256 * u;
            if ((BCH % 256 == 0) || (i < BCH)) {
                int r = i / NB4, c = (i % NB4) * 4;
                cp16(bbase + (unsigned int)(r * LDB + c) * 4,
                     &B[(size_t)(k0 + r) * N + bcol + c]);
            }
        }
    };

    const int ktiles = K / BK;

#pragma unroll
    for (int s = 0; s < STAGES - 1; s++) {
        if (s < ktiles) loadStage(s, s * BK);
        cp_commit();
    }

    for (int it = 0; it < ktiles; it++) {
        cp_wait<STAGES - 2>();
        __syncthreads();

        const int st = it % STAGES;
        const float* a0 = As + st * ASZ;
        const float* b0 = Bs + st * BSZ;
#pragma unroll
        for (int kk = 0; kk < BK; kk += 8) {
            wmma::fragment<wmma::matrix_a, 16, 16, 8, wmma::precision::tf32,
                           wmma::row_major> af[AM];
            wmma::fragment<wmma::matrix_b, 16, 16, 8, wmma::precision::tf32,
                           wmma::row_major> bf[NF];
#pragma unroll
            for (int i = 0; i < AM; i++)
                wmma::load_matrix_sync(af[i],
                    a0 + (wm * AM * 16 + i * 16) * LDA + kk, LDA);
#pragma unroll
            for (int j = 0; j < NF; j++)
                wmma::load_matrix_sync(bf[j],
                    b0 + kk * LDB + wn * NF * 16 + j * 16, LDB);
#pragma unroll
            for (int i = 0; i < AM; i++)
#pragma unroll
                for (int j = 0; j < NF; j++)
                    wmma::mma_sync(acc[i][j], af[i], bf[j], acc[i][j]);
        }

        const int nf = it + STAGES - 1;
        if (nf < ktiles) loadStage(nf % STAGES, nf * BK);
        cp_commit();
    }

    cp_wait<0>();
    __syncthreads();

    float* Ep = smem + wid * 256;
    const int er = lane >> 1;
    const int ec = (lane & 1) * 8;
#pragma unroll
    for (int i = 0; i < AM; i++) {
#pragma unroll
        for (int j = 0; j < NF; j++) {
            wmma::store_matrix_sync(Ep, acc[i][j], 16, wmma::mem_row_major);
            __syncwarp();
            int gr = brow + wm * AM * 16 + i * 16 + er;
            int gc = bcol + wn * NF * 16 + j * 16 + ec;
            float v[8];
#pragma unroll
            for (int q = 0; q < 8; q++) {
                float t = Ep[er * 16 + ec + q] + (bias ? bias[gc + q] : 0.f);
                v[q] = trunc_out ? wmma::__float_to_tf32(t) : t;
            }
            *(float4*)&C[(size_t)gr * N + gc]     = make_float4(v[0], v[1], v[2], v[3]);
            *(float4*)&C[(size_t)gr * N + gc + 4] = make_float4(v[4], v[5], v[6], v[7]);
            __syncwarp();
        }
    }
}

// ---------------------------------------------------------------------------
// Depthwise causal conv (K=4) + SiLU, float4-vectorized over d.
// ---------------------------------------------------------------------------
__global__ void conv_silu_v4(const float* __restrict__ cw,
                             const float* __restrict__ cb)
{
    int idx = blockIdx.x * blockDim.x + threadIdx.x;
    if (idx >= ROWS * (DI / 4)) return;
    int dv  = idx & (DI / 4 - 1);
    int row = idx >> 7;
    int t   = row & (TT - 1);
    int d   = dv * 4;

    const float* xi = g_xz + (size_t)row * (2 * DI) + d;
    float4 x0 = *(const float4*)xi;
    float4 x1 = (t >= 1) ? *(const float4*)(xi - 2 * DI) : make_float4(0, 0, 0, 0);
    float4 x2 = (t >= 2) ? *(const float4*)(xi - 4 * DI) : make_float4(0, 0, 0, 0);
    float4 x3 = (t >= 3) ? *(const float4*)(xi - 6 * DI) : make_float4(0, 0, 0, 0);

    float4 wa = *(const float4*)&cw[(d + 0) * 4];
    float4 wb = *(const float4*)&cw[(d + 1) * 4];
    float4 wc = *(const float4*)&cw[(d + 2) * 4];
    float4 wd = *(const float4*)&cw[(d + 3) * 4];
    float4 bc = *(const float4*)&cb[d];

    float4 acc;
    acc.x = bc.x + wa.w * x0.x + wa.z * x1.x + wa.y * x2.x + wa.x * x3.x;
    acc.y = bc.y + wb.w * x0.y + wb.z * x1.y + wb.y * x2.y + wb.x * x3.y;
    acc.z = bc.z + wc.w * x0.z + wc.z * x1.z + wc.y * x2.z + wc.x * x3.z;
    acc.w = bc.w + wd.w * x0.w + wd.z * x1.w + wd.y * x2.w + wd.x * x3.w;

    float4 o;
    o.x = wmma::__float_to_tf32(__fdividef(acc.x, 1.f + __expf(-acc.x)));
    o.y = wmma::__float_to_tf32(__fdividef(acc.y, 1.f + __expf(-acc.y)));
    o.z = wmma::__float_to_tf32(__fdividef(acc.z, 1.f + __expf(-acc.z)));
    o.w = wmma::__float_to_tf32(__fdividef(acc.w, 1.f + __expf(-acc.w)));
    *(float4*)&g_xc[(size_t)row * DI + d] = o;
}

// ===========================================================================
// Parallel selective scan: 3 passes over T split into GG groups of TG steps.
// Block = 128 thr = 32 d-lanes x 4 state-quads. dt computed in-kernel.
// ===========================================================================

// Pass 1: scan each group from h=0; store h_end (16 states x 32 lanes) and
// sum(dt) per lane (cross-group factor P_n = exp(a_n * sum_dt)).
__global__ __launch_bounds__(128) void scan_part(
    const float* __restrict__ A_log_l,
    const float* __restrict__ Wdt_l, const float* __restrict__ bdt_l)
{
    __shared__ __align__(16) float s_dt[2][SCH][32];
    __shared__ __align__(16) float s_x [2][SCH][32];
    __shared__ __align__(16) float s_db[2][SCH][52];
    __shared__ float s_wdt[16][33];

    const int bx  = blockIdx.x;            // [0, BB*16*GG)
    const int b   = bx / (16 * GG);
    const int rem = bx % (16 * GG);
    const int g   = rem >> 4;
    const int dg  = rem & 15;
    const int d0  = dg * 32;
    const int tid = threadIdx.x;
    const int q   = tid & 3;
    const int dl  = tid >> 2;
    const int d   = d0 + dl;

    const int tl  = tid >> 3;
    const int seg = tid & 7;

    const int r0 = tid / 12,         c0 = tid % 12;
    const int r1 = (tid + 128) / 12, c1 = (tid + 128) % 12;
    const bool ld1 = (tid < 64);

    for (int i = tid; i < 16 * 32; i += 128)
        s_wdt[i >> 5][i & 31] = Wdt_l[(i >> 5) * DI + d0 + (i & 31)];
    float bdt4[4];
#pragma unroll
    for (int j = 0; j < 4; j++)
        bdt4[j] = bdt_l[d0 + seg * 4 + j];

    float a[4];
#pragma unroll
    for (int j = 0; j < 4; j++)
        a[j] = -__expf(A_log_l[d * NST + q * 4 + j]);

    const size_t rb = (size_t)b * TT + (size_t)g * TG;

    float h0 = 0.f, h1 = 0.f, h2 = 0.f, h3 = 0.f;
    float sdt = 0.f;

    auto computeDt = [&](int bf) {
        float a0 = bdt4[0], a1 = bdt4[1], a2 = bdt4[2], a3 = bdt4[3];
#pragma unroll
        for (int r = 0; r < 16; r++) {
            float dbv = s_db[bf][tl][r];
            a0 += dbv * s_wdt[r][seg * 4 + 0];
            a1 += dbv * s_wdt[r][seg * 4 + 1];
            a2 += dbv * s_wdt[r][seg * 4 + 2];
            a3 += dbv * s_wdt[r][seg * 4 + 3];
        }
        s_dt[bf][tl][seg * 4 + 0] = (a0 > 20.f) ? a0 : log1pf(__expf(a0));
        s_dt[bf][tl][seg * 4 + 1] = (a1 > 20.f) ? a1 : log1pf(__expf(a1));
        s_dt[bf][tl][seg * 4 + 2] = (a2 > 20.f) ? a2 : log1pf(__expf(a2));
        s_dt[bf][tl][seg * 4 + 3] = (a3 > 20.f) ? a3 : log1pf(__expf(a3));
    };

    {
        size_t row = rb + tl;
        *(float4*)&s_x [0][tl][seg * 4] = *(const float4*)&g_xc[row * DI + d0 + seg * 4];
        *(float4*)&s_db[0][r0][c0 * 4]  = *(const float4*)&g_dbc[(rb + r0) * DBCN + c0 * 4];
        if (ld1)
            *(float4*)&s_db[0][r1][c1 * 4] = *(const float4*)&g_dbc[(rb + r1) * DBCN + c1 * 4];
    }
    __syncthreads();
    computeDt(0);
    __syncthreads();

    int buf = 0;
    const int NC = TG / SCH;
    for (int c = 0; c < NC; c++) {
        float4 vx, vdb0, vdb1;
        const bool more = (c + 1 < NC);
        if (more) {
            size_t cro = rb + (size_t)(c + 1) * SCH;
            vx   = *(const float4*)&g_xc[(cro + tl) * DI + d0 + seg * 4];
            vdb0 = *(const float4*)&g_dbc[(cro + r0) * DBCN + c0 * 4];
            if (ld1) vdb1 = *(const float4*)&g_dbc[(cro + r1) * DBCN + c1 * 4];
        }

#pragma unroll
        for (int it = 0; it < SCH; it++) {
            float dt  = s_dt[buf][it][dl];
            float x   = s_x [buf][it][dl];
            float4 Bv = *(const float4*)&s_db[buf][it][RR + q * 4];

            float dtx = dt * x;
            h0 = __expf(dt * a[0]) * h0 + dtx * Bv.x;
            h1 = __expf(dt * a[1]) * h1 + dtx * Bv.y;
            h2 = __expf(dt * a[2]) * h2 + dtx * Bv.z;
            h3 = __expf(dt * a[3]) * h3 + dtx * Bv.w;
            sdt += dt;
        }

        if (more) {
            *(float4*)&s_x [buf ^ 1][tl][seg * 4] = vx;
            *(float4*)&s_db[buf ^ 1][r0][c0 * 4]  = vdb0;
            if (ld1)
                *(float4*)&s_db[buf ^ 1][r1][c1 * 4] = vdb1;
            __syncthreads();
            computeDt(buf ^ 1);
            __syncthreads();
        }
        buf ^= 1;
    }

    const size_t base = ((size_t)(b * 16 + dg) * GG + g) * 512;
    g_hend[base + (q * 4 + 0) * 32 + dl] = h0;
    g_hend[base + (q * 4 + 1) * 32 + dl] = h1;
    g_hend[base + (q * 4 + 2) * 32 + dl] = h2;
    g_hend[base + (q * 4 + 3) * 32 + dl] = h3;
    if (q == 0)
        g_sdt[(size_t)(b * 16 + dg) * GG * 32 + (size_t)g * 32 + dl] = sdt;
}

// Pass 2: sequential combine across groups (tiny).
__global__ __launch_bounds__(128) void scan_combine(const float* __restrict__ A_log_l)
{
    const int bx  = blockIdx.x;   // [0, BB*16)
    const int dg  = bx & 15;
    const int tid = threadIdx.x;
    const int q   = tid & 3;
    const int dl  = tid >> 2;
    const int d   = dg * 32 + dl;

    float a[4];
#pragma unroll
    for (int j = 0; j < 4; j++)
        a[j] = -__expf(A_log_l[d * NST + q * 4 + j]);

    float H[4] = {0.f, 0.f, 0.f, 0.f};
#pragma unroll
    for (int g = 0; g < GG; g++) {
        const size_t base = ((size_t)bx * GG + g) * 512;
#pragma unroll
        for (int j = 0; j < 4; j++)
            g_hin[base + (q * 4 + j) * 32 + dl] = H[j];
        float S = g_sdt[(size_t)bx * GG * 32 + (size_t)g * 32 + dl];
#pragma unroll
        for (int j = 0; j < 4; j++)
            H[j] = __expf(a[j] * S) * H[j] + g_hend[base + (q * 4 + j) * 32 + dl];
    }
}

// Pass 3: rescan each group from its true h_in; emit gated y.
__global__ __launch_bounds__(128) void scan_emit(
    const float* __restrict__ A_log_l, const float* __restrict__ Dp_l,
    const float* __restrict__ Wdt_l,   const float* __restrict__ bdt_l)
{
    __shared__ __align__(16) float s_dt[2][SCH][32];
    __shared__ __align__(16) float s_x [2][SCH][32];
    __shared__ __align__(16) float s_z [2][SCH][32];
    __shared__ __align__(16) float s_db[2][SCH][52];
    __shared__ float s_wdt[16][33];

    const int bx  = blockIdx.x;
    const int b   = bx / (16 * GG);
    const int rem = bx % (16 * GG);
    const int g   = rem >> 4;
    const int dg  = rem & 15;
    const int d0  = dg * 32;
    const int tid = threadIdx.x;
    const int q   = tid & 3;
    const int dl  = tid >> 2;
    const int d   = d0 + dl;

    const int tl  = tid >> 3;
    const int seg = tid & 7;

    const int r0 = tid / 12,         c0 = tid % 12;
    const int r1 = (tid + 128) / 12, c1 = (tid + 128) % 12;
    const bool ld1 = (tid < 64);

    for (int i = tid; i < 16 * 32; i += 128)
        s_wdt[i >> 5][i & 31] = Wdt_l[(i >> 5) * DI + d0 + (i & 31)];
    float bdt4[4];
#pragma unroll
    for (int j = 0; j < 4; j++)
        bdt4[j] = bdt_l[d0 + seg * 4 + j];

    float a[4];
#pragma unroll
    for (int j = 0; j < 4; j++)
        a[j] = -__expf(A_log_l[d * NST + q * 4 + j]);
    const float dp = Dp_l[d];

    const size_t rb = (size_t)b * TT + (size_t)g * TG;

    const size_t base = ((size_t)(b * 16 + dg) * GG + g) * 512;
    float h0 = g_hin[base + (q * 4 + 0) * 32 + dl];
    float h1 = g_hin[base + (q * 4 + 1) * 32 + dl];
    float h2 = g_hin[base + (q * 4 + 2) * 32 + dl];
    float h3 = g_hin[base + (q * 4 + 3) * 32 + dl];

    auto computeDt = [&](int bf) {
        float a0 = bdt4[0], a1 = bdt4[1], a2 = bdt4[2], a3 = bdt4[3];
#pragma unroll
        for (int r = 0; r < 16; r++) {
            float dbv = s_db[bf][tl][r];
            a0 += dbv * s_wdt[r][seg * 4 + 0];
            a1 += dbv * s_wdt[r][seg * 4 + 1];
            a2 += dbv * s_wdt[r][seg * 4 + 2];
            a3 += dbv * s_wdt[r][seg * 4 + 3];
        }
        s_dt[bf][tl][seg * 4 + 0] = (a0 > 20.f) ? a0 : log1pf(__expf(a0));
        s_dt[bf][tl][seg * 4 + 1] = (a1 > 20.f) ? a1 : log1pf(__expf(a1));
        s_dt[bf][tl][seg * 4 + 2] = (a2 > 20.f) ? a2 : log1pf(__expf(a2));
        s_dt[bf][tl][seg * 4 + 3] = (a3 > 20.f) ? a3 : log1pf(__expf(a3));
    };

    {
        size_t row = rb + tl;
        *(float4*)&s_x [0][tl][seg * 4] = *(const float4*)&g_xc[row * DI + d0 + seg * 4];
        *(float4*)&s_z [0][tl][seg * 4] = *(const float4*)&g_xz[row * (2 * DI) + DI + d0 + seg * 4];
        *(float4*)&s_db[0][r0][c0 * 4]  = *(const float4*)&g_dbc[(rb + r0) * DBCN + c0 * 4];
        if (ld1)
            *(float4*)&s_db[0][r1][c1 * 4] = *(const float4*)&g_dbc[(rb + r1) * DBCN + c1 * 4];
    }
    __syncthreads();
    computeDt(0);
    __syncthreads();

    int buf = 0;
    const int NC = TG / SCH;
    for (int c = 0; c < NC; c++) {
        float4 vx, vz, vdb0, vdb1;
        const bool more = (c + 1 < NC);
        if (more) {
            size_t cro = rb + (size_t)(c + 1) * SCH;
            size_t row = cro + tl;
            vx   = *(const float4*)&g_xc[row * DI + d0 + seg * 4];
            vz   = *(const float4*)&g_xz[row * (2 * DI) + DI + d0 + seg * 4];
            vdb0 = *(const float4*)&g_dbc[(cro + r0) * DBCN + c0 * 4];
            if (ld1) vdb1 = *(const float4*)&g_dbc[(cro + r1) * DBCN + c1 * 4];
        }

#pragma unroll
        for (int it = 0; it < SCH; it++) {
            float dt  = s_dt[buf][it][dl];
            float x   = s_x [buf][it][dl];
            float4 Bv = *(const float4*)&s_db[buf][it][RR + q * 4];
            float4 Cv = *(const float4*)&s_db[buf][it][RR + NST + q * 4];
            float z   = s_z [buf][it][dl];

            float dtx = dt * x;
            h0 = __expf(dt * a[0]) * h0 + dtx * Bv.x;
            h1 = __expf(dt * a[1]) * h1 + dtx * Bv.y;
            h2 = __expf(dt * a[2]) * h2 + dtx * Bv.z;
            h3 = __expf(dt * a[3]) * h3 + dtx * Bv.w;

            float pv = h0 * Cv.x + h1 * Cv.y + h2 * Cv.z + h3 * Cv.w;
            pv += __shfl_xor_sync(0xffffffffu, pv, 1);
            pv += __shfl_xor_sync(0xffffffffu, pv, 2);

            if (q == 0) {
                float sz = __fdividef(z, 1.f + __expf(-z));
                size_t row = rb + (size_t)c * SCH + it;
                g_y[row * DI + d] = wmma::__float_to_tf32((pv + dp * x) * sz);
            }
        }

        if (more) {
            *(float4*)&s_x [buf ^ 1][tl][seg * 4] = vx;
            *(float4*)&s_z [buf ^ 1][tl][seg * 4] = vz;
            *(float4*)&s_db[buf ^ 1][r0][c0 * 4]  = vdb0;
            if (ld1)
                *(float4*)&s_db[buf ^ 1][r1][c1 * 4] = vdb1;
            __syncthreads();
            computeDt(buf ^ 1);
            __syncthreads();
        }
        buf ^= 1;
    }
}

// ---------------------------------------------------------------------------
// Mean over T (two-stage) + out-projection
// ---------------------------------------------------------------------------
__global__ void mean_part()
{
    int b = blockIdx.x >> 5;
    int c = blockIdx.x & 31;
    int col = threadIdx.x;

    const float* hp = g_h + ((size_t)b * TT + (size_t)c * 64) * DM + col;
    float s = 0.f;
#pragma unroll 8
    for (int t = 0; t < 64; t++)
        s += hp[(size_t)t * DM];
    g_part[(b * 32 + c) * DM + col] = s;
}

__global__ void mean_proj2(const float* __restrict__ Wop,
                           const float* __restrict__ bop,
                           float* __restrict__ out)
{
    __shared__ float hm[DM];
    int b = blockIdx.x;
    int c = threadIdx.x;

    float s = 0.f;
#pragma unroll
    for (int i = 0; i < 32; i++)
        s += g_part[(b * 32 + i) * DM + c];
    hm[c] = s * (1.f / (float)TT);
    __syncthreads();

    if (c < DOUT) {
        float acc = bop[c];
#pragma unroll 4
        for (int k = 0; k < DM; k++)
            acc += hm[k] * Wop[k * DOUT + c];
        out[b * DOUT + c] = acc;
    }
}

// ---------------------------------------------------------------------------
// Orchestration
// ---------------------------------------------------------------------------
static constexpr int SMEM_T(int BN)
{
    return 4 * (128 * 20 + 16 * (BN + 4)) * 4;
}

extern "C" void kernel_launch(void* const* d_in, const int* in_sizes, int n_in,
                              void* d_out, int out_size)
{
    const float* x        = (const float*)d_in[0];
    const float* W_in     = (const float*)d_in[1];
    const float* b_in     = (const float*)d_in[2];
    const float* Win      = (const float*)d_in[3];
    const float* bin_     = (const float*)d_in[4];
    const float* conv_w   = (const float*)d_in[5];
    const float* conv_b   = (const float*)d_in[6];
    const float* Wx       = (const float*)d_in[7];
    const float* Wdt      = (const float*)d_in[8];
    const float* bdt      = (const float*)d_in[9];
    const float* A_log    = (const float*)d_in[10];
    const float* Dp       = (const float*)d_in[11];
    const float* Wout     = (const float*)d_in[12];
    const float* W_op     = (const float*)d_in[13];
    const float* b_op     = (const float*)d_in[14];
    float* out = (float*)d_out;

    float *hbuf, *xzbuf, *xcbuf, *dbcbuf, *ybuf, *wt, *xtf;
    cudaGetSymbolAddress((void**)&hbuf,   g_h);
    cudaGetSymbolAddress((void**)&xzbuf,  g_xz);
    cudaGetSymbolAddress((void**)&xcbuf,  g_xc);
    cudaGetSymbolAddress((void**)&dbcbuf, g_dbc);
    cudaGetSymbolAddress((void**)&ybuf,   g_y);
    cudaGetSymbolAddress((void**)&wt,     g_wt);
    cudaGetSymbolAddress((void**)&xtf,    g_xtf);

    constexpr int SM128 = SMEM_T(128);
    constexpr int SM48  = SMEM_T(48);
    cudaFuncSetAttribute(tgemm<128, 4>, cudaFuncAttributeMaxDynamicSharedMemorySize, SM128);
    cudaFuncSetAttribute(tgemm<48, 8>,  cudaFuncAttributeMaxDynamicSharedMemorySize, SM48);

    // launch 1: truncate weights
    {
        CvtJobs jobs;
        jobs.j[0] = { W_in, wt + W_IN_OFF, DIN * DM          };
        jobs.j[1] = { Win,  wt + WIN_OFF,  LAY * DM * 2 * DI };
        jobs.j[2] = { Wx,   wt + WX_OFF,   LAY * DI * DBCN   };
        jobs.j[3] = { Wout, wt + WOUT_OFF, LAY * DI * DM     };
        int total = 0;
        for (int k = 0; k < 4; k++) total += jobs.j[k].n;
        tf32_cvt_multi<<<(total + 255) / 256, 256>>>(jobs, total);
    }
    // launch 2: truncate x
    tf32_cvt<<<(ROWS * DIN + 255) / 256, 256>>>(x, xtf, ROWS * DIN);

    // launch 3: in_proj
    {
        dim3 g(DM / 128, ROWS / 128);
        tgemm<128, 4><<<g, 256, SM128>>>(xtf, wt + W_IN_OFF, b_in, hbuf,
                                         ROWS, DM, DIN, 1);
    }

    const int CONV_BLOCKS = (ROWS * (DI / 4) + 255) / 256;

    for (int l = 0; l < LAY; l++) {
        const float* Win_l  = wt + WIN_OFF  + (size_t)l * DM * 2 * DI;
        const float* bin_l  = bin_   + (size_t)l * 2 * DI;
        const float* cw_l   = conv_w + (size_t)l * DI * 4;
        const float* cb_l   = conv_b + (size_t)l * DI;
        const float* Wx_l   = wt + WX_OFF   + (size_t)l * DI * DBCN;
        const float* Wdt_l  = Wdt    + (size_t)l * RR * DI;
        const float* bdt_l  = bdt    + (size_t)l * DI;
        const float* Alog_l = A_log  + (size_t)l * DI * NST;
        const float* Dp_l   = Dp     + (size_t)l * DI;
        const float* Wout_l = wt + WOUT_OFF + (size_t)l * DI * DM;

        // launch 4 (l=0): xz GEMM -> profiled slot
        {
            dim3 g((2 * DI) / 128, ROWS / 128);
            tgemm<128, 4><<<g, 256, SM128>>>(hbuf, Win_l, bin_l, xzbuf,
                                             ROWS, 2 * DI, DM, 0);
        }
        // conv
        conv_silu_v4<<<CONV_BLOCKS, 256>>>(cw_l, cb_l);
        // dbc = xc @ Wx  (single GEMM, no split-K)
        {
            dim3 g(1, ROWS / 128);
            tgemm<48, 8><<<g, 256, SM48>>>(xcbuf, Wx_l, nullptr, dbcbuf,
                                           ROWS, DBCN, DI, 0);
        }
        // parallel scan: part -> combine -> emit
        scan_part   <<<BB * 16 * GG, 128>>>(Alog_l, Wdt_l, bdt_l);
        scan_combine<<<BB * 16,      128>>>(Alog_l);
        scan_emit   <<<BB * 16 * GG, 128>>>(Alog_l, Dp_l, Wdt_l, bdt_l);
        // h = y @ Wout
        {
            dim3 g(DM / 128, ROWS / 128);
            tgemm<128, 4><<<g, 256, SM128>>>(ybuf, Wout_l, nullptr, hbuf,
                                             ROWS, DM, DI, 1);
        }
    }

    mean_part<<<BB * 32, DM>>>();
    mean_proj2<<<BB, DM>>>(W_op, b_op, out);
}

// round 10
// speedup vs baseline: 2.2124x; 1.3209x over previous
#include <cuda_runtime.h>
#include <cstdint>
#include <math.h>
#include <mma.h>

using namespace nvcuda;

// Problem constants
#define BB   8
#define TT   2048
#define ROWS (BB * TT)      // 16384
#define DIN  64
#define DM   256
#define DI   512
#define NST  16
#define RR   16
#define DOUT 128
#define DBCN 48             // R + 2N
#define LAY  2
// parallel scan split
#define GG   8
#define TG   (TT / GG)
#define SCH  16

// ---------------------------------------------------------------------------
// Scratch (static device globals)
// ---------------------------------------------------------------------------
__device__ float g_h   [ROWS * DM];
__device__ float g_xz  [ROWS * 2 * DI];
__device__ float g_xc  [ROWS * DI];
__device__ float g_dbc [ROWS * DBCN];
__device__ float g_y   [ROWS * DI];
__device__ float g_part[BB * 32 * DM];
__device__ float g_hend[BB * 16 * GG * 512];
__device__ float g_hin [BB * 16 * GG * 512];
__device__ float g_sdt [BB * 16 * GG * 32];
// tf32 weights (wmma dbc path, original [K,N] layout)
#define WX_OFF    0
#define WT_TOTAL  (WX_OFF + LAY * DI * DBCN)
__device__ float g_wt [WT_TOTAL];
// tf32 TRANSPOSED weights [N,K] for mma.sync path
#define WINT_OFF  0                           // [LAY][2*DI][DM]
#define WOUTT_OFF (LAY * 2 * DI * DM)         // [LAY][DM][DI]
#define WINPT_OFF (WOUTT_OFF + LAY * DM * DI) // [DM][DIN]
#define WTT_TOTAL (WINPT_OFF + DM * DIN)
__device__ float g_wtT[WTT_TOTAL];
__device__ float g_xtf[ROWS * DIN];

// ---------------------------------------------------------------------------
// tf32 truncation kernels
// ---------------------------------------------------------------------------
struct CvtJob  { const float* src; float* dst; int n; };
struct CvtJobs { CvtJob j[2]; };

__global__ void tf32_cvt_multi(CvtJobs jobs, int total)
{
    int i = blockIdx.x * blockDim.x + threadIdx.x;
    if (i >= total) return;
#pragma unroll
    for (int k = 0; k < 2; k++) {
        if (i < jobs.j[k].n) {
            jobs.j[k].dst[i] = wmma::__float_to_tf32(jobs.j[k].src[i]);
            return;
        }
        i -= jobs.j[k].n;
    }
}

// transpose+truncate Win, Wout, W_in into [N,K] layout for mma B operand
__global__ void cvt_T(const float* __restrict__ Win, const float* __restrict__ Wout,
                      const float* __restrict__ W_in,
                      float* __restrict__ WinT, float* __restrict__ WoutT,
                      float* __restrict__ WinpT)
{
    int i = blockIdx.x * blockDim.x + threadIdx.x;
    if (i < LAY * 2 * DI * DM) {
        int l = i / (2 * DI * DM);
        int r = i % (2 * DI * DM);
        int n = r / DM;
        int k = r % DM;
        WinT[i] = wmma::__float_to_tf32(Win[(size_t)l * 2 * DI * DM + (size_t)k * (2 * DI) + n]);
        return;
    }
    i -= LAY * 2 * DI * DM;
    if (i < LAY * DM * DI) {
        int l = i / (DM * DI);
        int r = i % (DM * DI);
        int n = r / DI;
        int k = r % DI;
        WoutT[i] = wmma::__float_to_tf32(Wout[(size_t)l * DM * DI + (size_t)k * DM + n]);
        return;
    }
    i -= LAY * DM * DI;
    if (i < DM * DIN) {
        int n = i / DIN;
        int k = i % DIN;
        WinpT[i] = wmma::__float_to_tf32(W_in[(size_t)k * DM + n]);
    }
}

// ---------------------------------------------------------------------------
// cp.async helpers
// ---------------------------------------------------------------------------
__device__ __forceinline__ void cp16(unsigned int smem_addr, const float* gptr)
{
    asm volatile("cp.async.cg.shared.global [%0], [%1], 16;\n"
                 :: "r"(smem_addr), "l"(gptr));
}
__device__ __forceinline__ void cp_commit()
{
    asm volatile("cp.async.commit_group;\n");
}
template<int N>
__device__ __forceinline__ void cp_wait()
{
    asm volatile("cp.async.wait_group %0;\n" :: "n"(N));
}
__device__ __forceinline__ unsigned int smem_u32_of(const void* p)
{
    unsigned int a;
    asm("{ .reg .u64 t; cvta.to.shared.u64 t, %1; cvt.u32.u64 %0, t; }"
        : "=r"(a) : "l"(p));
    return a;
}

// ---------------------------------------------------------------------------
// mma.sync helpers (tf32 m16n8k8, ldmatrix fragment loads)
// ---------------------------------------------------------------------------
__device__ __forceinline__ void ldsm_x4(uint32_t& r0, uint32_t& r1,
                                        uint32_t& r2, uint32_t& r3,
                                        unsigned int addr)
{
    asm volatile("ldmatrix.sync.aligned.m8n8.x4.shared.b16 {%0,%1,%2,%3}, [%4];"
                 : "=r"(r0), "=r"(r1), "=r"(r2), "=r"(r3) : "r"(addr));
}
__device__ __forceinline__ void mma_tf32(float* d, const uint32_t* a, const uint32_t* b)
{
    asm volatile("mma.sync.aligned.m16n8k8.row.col.f32.tf32.tf32.f32 "
                 "{%0,%1,%2,%3}, {%4,%5,%6,%7}, {%8,%9}, {%0,%1,%2,%3};"
                 : "+f"(d[0]), "+f"(d[1]), "+f"(d[2]), "+f"(d[3])
                 : "r"(a[0]), "r"(a[1]), "r"(a[2]), "r"(a[3]),
                   "r"(b[0]), "r"(b[1]));
}

// ---------------------------------------------------------------------------
// mma.sync TF32 GEMM: C[M,N] = A[M,K] @ Bt[N,K]^T (+ bias).
// CTA tile 128x128, BK=16, 4-stage cp.async, 8 warps (4m x 2n), warp 32x64.
// Fragment loads via ldmatrix.x4.b16, row stride 80B (conflict-free).
// Requires M%128==0, N%128==0, K%16==0, K>=48.
// ---------------------------------------------------------------------------
#define MST   4
#define MROWB 80
#define MASZ  (128 * MROWB)          // 10240 B per operand per stage
#define MSMEM (2 * MST * MASZ)       // 81920 B

__global__ __launch_bounds__(256, 2) void mgemm(
    const float* __restrict__ A, const float* __restrict__ Bt,
    const float* __restrict__ bias, float* __restrict__ C,
    int M, int N, int K, int trunc_out)
{
    extern __shared__ char msm[];
    char* As = msm;
    char* Bs = msm + MST * MASZ;

    const int tid  = threadIdx.x;
    const int lane = tid & 31;
    const int wid  = tid >> 5;
    const int wm   = wid & 3;           // 0..3 -> rows wm*32
    const int wn   = wid >> 2;          // 0..1 -> cols wn*64
    const int brow = blockIdx.y * 128;
    const int bcol = blockIdx.x * 128;

    float acc[2][8][4];
#pragma unroll
    for (int i = 0; i < 2; i++)
#pragma unroll
        for (int j = 0; j < 8; j++)
#pragma unroll
            for (int q = 0; q < 4; q++) acc[i][j][q] = 0.f;

    const unsigned int asmb = smem_u32_of(As);
    const unsigned int bsmb = smem_u32_of(Bs);

    const int lr  = tid >> 2;            // 0..63
    const int lcB = (tid & 3) * 16;      // byte col 0/16/32/48

    auto loadStage = [&](int st, int k0) {
        unsigned int ab = asmb + st * MASZ;
        unsigned int bb = bsmb + st * MASZ;
#pragma unroll
        for (int u = 0; u < 2; u++) {
            int r = lr + u * 64;
            cp16(ab + r * MROWB + lcB, &A [(size_t)(brow + r) * K + k0 + (lcB >> 2)]);
            cp16(bb + r * MROWB + lcB, &Bt[(size_t)(bcol + r) * K + k0 + (lcB >> 2)]);
        }
    };

    const int ktiles = K / 16;
#pragma unroll
    for (int s = 0; s < MST - 1; s++) {
        if (s < ktiles) loadStage(s, s * 16);
        cp_commit();
    }

    const int mq = lane >> 3;            // matrix quad 0..3
    const int r8 = lane & 7;

    for (int kt = 0; kt < ktiles; kt++) {
        cp_wait<MST - 2>();
        __syncthreads();

        const int st = kt % MST;
        const unsigned int ab = asmb + st * MASZ;
        const unsigned int bb = bsmb + st * MASZ;
#pragma unroll
        for (int s = 0; s < 2; s++) {    // two k8 slices per ktile
            uint32_t af[2][4];
#pragma unroll
            for (int i = 0; i < 2; i++) {
                unsigned int row  = wm * 32 + i * 16 + (mq & 1) * 8 + r8;
                unsigned int addr = ab + row * MROWB + s * 32 + (mq >> 1) * 16;
                ldsm_x4(af[i][0], af[i][1], af[i][2], af[i][3], addr);
            }
            uint32_t bf[8][2];
#pragma unroll
            for (int jp = 0; jp < 4; jp++) {
                unsigned int row  = wn * 64 + jp * 16 + (mq >> 1) * 8 + r8;
                unsigned int addr = bb + row * MROWB + s * 32 + (mq & 1) * 16;
                uint32_t t0, t1, t2, t3;
                ldsm_x4(t0, t1, t2, t3, addr);
                bf[jp * 2 + 0][0] = t0;  bf[jp * 2 + 0][1] = t1;
                bf[jp * 2 + 1][0] = t2;  bf[jp * 2 + 1][1] = t3;
            }
#pragma unroll
            for (int i = 0; i < 2; i++)
#pragma unroll
                for (int j = 0; j < 8; j++)
                    mma_tf32(acc[i][j], af[i], bf[j]);
        }

        const int nf = kt + MST - 1;
        if (nf < ktiles) loadStage(nf % MST, nf * 16);
        cp_commit();
    }
    cp_wait<0>();

    // epilogue: accum layout c0,c1 = (g, 2c..2c+1), c2,c3 = (g+8, same)
    const int g  = lane >> 2;
    const int c2 = (lane & 3) * 2;
#pragma unroll
    for (int i = 0; i < 2; i++) {
#pragma unroll
        for (int j = 0; j < 8; j++) {
            int gr = brow + wm * 32 + i * 16 + g;
            int gc = bcol + wn * 64 + j * 8 + c2;
            float b0 = bias ? bias[gc]     : 0.f;
            float b1 = bias ? bias[gc + 1] : 0.f;
            float v0 = acc[i][j][0] + b0, v1 = acc[i][j][1] + b1;
            float v2 = acc[i][j][2] + b0, v3 = acc[i][j][3] + b1;
            if (trunc_out) {
                v0 = wmma::__float_to_tf32(v0);
                v1 = wmma::__float_to_tf32(v1);
                v2 = wmma::__float_to_tf32(v2);
                v3 = wmma::__float_to_tf32(v3);
            }
            *(float2*)&C[(size_t)gr * N + gc]       = make_float2(v0, v1);
            *(float2*)&C[(size_t)(gr + 8) * N + gc] = make_float2(v2, v3);
        }
    }
}

// ---------------------------------------------------------------------------
// wmma TF32 GEMM (kept for dbc), 4-stage cp.async pipeline.
// ---------------------------------------------------------------------------
template<int BN, int WM>
__global__ __launch_bounds__(256, 2) void tgemm(
    const float* __restrict__ A, const float* __restrict__ B,
    const float* __restrict__ bias, float* __restrict__ C,
    int M, int N, int K, int trunc_out)
{
    constexpr int BM = 128, BK = 16, STAGES = 4;
    constexpr int LDA = BK + 4;
    constexpr int LDB = BN + 4;
    constexpr int ASZ = BM * LDA;
    constexpr int BSZ = BK * LDB;
    constexpr int WNW = 8 / WM;
    constexpr int AM  = BM / (WM * 16);
    constexpr int NF  = BN / (WNW * 16);
    constexpr int NB4 = BN / 4;
    constexpr int BCH = BK * BN / 4;

    extern __shared__ float smem[];
    float* As = smem;
    float* Bs = smem + STAGES * ASZ;

    const int tid  = threadIdx.x;
    const int lane = tid & 31;
    const int wid  = tid >> 5;
    const int wm   = wid % WM;
    const int wn   = wid / WM;
    const int brow = blockIdx.y * BM;
    const int bcol = blockIdx.x * BN;

    wmma::fragment<wmma::accumulator, 16, 16, 8, float> acc[AM][NF];
#pragma unroll
    for (int i = 0; i < AM; i++)
#pragma unroll
        for (int j = 0; j < NF; j++)
            wmma::fill_fragment(acc[i][j], 0.f);

    const int ar0 = tid >> 2;
    const int ar1 = (tid + 256) >> 2;
    const int ac  = (tid & 3) * 4;

    auto loadStage = [&](int st, int k0) {
        unsigned int abase = (unsigned int)__cvta_generic_to_shared(As + st * ASZ);
        cp16(abase + (unsigned int)(ar0 * LDA + ac) * 4,
             &A[(size_t)(brow + ar0) * K + k0 + ac]);
        cp16(abase + (unsigned int)(ar1 * LDA + ac) * 4,
             &A[(size_t)(brow + ar1) * K + k0 + ac]);
        unsigned int bbase = (unsigned int)__cvta_generic_to_shared(Bs + st * BSZ);
#pragma unroll
        for (int u = 0; u < (BCH + 255) / 256; u++) {
            int i = tid + 256 * u;
            if ((BCH % 256 == 0) || (i < BCH)) {
                int r = i / NB4, c = (i % NB4) * 4;
                cp16(bbase + (unsigned int)(r * LDB + c) * 4,
                     &B[(size_t)(k0 + r) * N + bcol + c]);
            }
        }
    };

    const int ktiles = K / BK;

#pragma unroll
    for (int s = 0; s < STAGES - 1; s++) {
        if (s < ktiles) loadStage(s, s * BK);
        cp_commit();
    }

    for (int it = 0; it < ktiles; it++) {
        cp_wait<STAGES - 2>();
        __syncthreads();

        const int st = it % STAGES;
        const float* a0 = As + st * ASZ;
        const float* b0 = Bs + st * BSZ;
#pragma unroll
        for (int kk = 0; kk < BK; kk += 8) {
            wmma::fragment<wmma::matrix_a, 16, 16, 8, wmma::precision::tf32,
                           wmma::row_major> af[AM];
            wmma::fragment<wmma::matrix_b, 16, 16, 8, wmma::precision::tf32,
                           wmma::row_major> bf[NF];
#pragma unroll
            for (int i = 0; i < AM; i++)
                wmma::load_matrix_sync(af[i],
                    a0 + (wm * AM * 16 + i * 16) * LDA + kk, LDA);
#pragma unroll
            for (int j = 0; j < NF; j++)
                wmma::load_matrix_sync(bf[j],
                    b0 + kk * LDB + wn * NF * 16 + j * 16, LDB);
#pragma unroll
            for (int i = 0; i < AM; i++)
#pragma unroll
                for (int j = 0; j < NF; j++)
                    wmma::mma_sync(acc[i][j], af[i], bf[j], acc[i][j]);
        }

        const int nf = it + STAGES - 1;
        if (nf < ktiles) loadStage(nf % STAGES, nf * BK);
        cp_commit();
    }

    cp_wait<0>();
    __syncthreads();

    float* Ep = smem + wid * 256;
    const int er = lane >> 1;
    const int ec = (lane & 1) * 8;
#pragma unroll
    for (int i = 0; i < AM; i++) {
#pragma unroll
        for (int j = 0; j < NF; j++) {
            wmma::store_matrix_sync(Ep, acc[i][j], 16, wmma::mem_row_major);
            __syncwarp();
            int gr = brow + wm * AM * 16 + i * 16 + er;
            int gc = bcol + wn * NF * 16 + j * 16 + ec;
            float v[8];
#pragma unroll
            for (int q = 0; q < 8; q++) {
                float t = Ep[er * 16 + ec + q] + (bias ? bias[gc + q] : 0.f);
                v[q] = trunc_out ? wmma::__float_to_tf32(t) : t;
            }
            *(float4*)&C[(size_t)gr * N + gc]     = make_float4(v[0], v[1], v[2], v[3]);
            *(float4*)&C[(size_t)gr * N + gc + 4] = make_float4(v[4], v[5], v[6], v[7]);
            __syncwarp();
        }
    }
}

// ---------------------------------------------------------------------------
// Depthwise causal conv (K=4) + SiLU, float4 over d.
// ---------------------------------------------------------------------------
__global__ void conv_silu_v4(const float* __restrict__ cw,
                             const float* __restrict__ cb)
{
    int idx = blockIdx.x * blockDim.x + threadIdx.x;
    if (idx >= ROWS * (DI / 4)) return;
    int dv  = idx & (DI / 4 - 1);
    int row = idx >> 7;
    int t   = row & (TT - 1);
    int d   = dv * 4;

    const float* xi = g_xz + (size_t)row * (2 * DI) + d;
    float4 x0 = *(const float4*)xi;
    float4 x1 = (t >= 1) ? *(const float4*)(xi - 2 * DI) : make_float4(0, 0, 0, 0);
    float4 x2 = (t >= 2) ? *(const float4*)(xi - 4 * DI) : make_float4(0, 0, 0, 0);
    float4 x3 = (t >= 3) ? *(const float4*)(xi - 6 * DI) : make_float4(0, 0, 0, 0);

    float4 wa = *(const float4*)&cw[(d + 0) * 4];
    float4 wb = *(const float4*)&cw[(d + 1) * 4];
    float4 wc = *(const float4*)&cw[(d + 2) * 4];
    float4 wd = *(const float4*)&cw[(d + 3) * 4];
    float4 bc = *(const float4*)&cb[d];

    float4 acc;
    acc.x = bc.x + wa.w * x0.x + wa.z * x1.x + wa.y * x2.x + wa.x * x3.x;
    acc.y = bc.y + wb.w * x0.y + wb.z * x1.y + wb.y * x2.y + wb.x * x3.y;
    acc.z = bc.z + wc.w * x0.z + wc.z * x1.z + wc.y * x2.z + wc.x * x3.z;
    acc.w = bc.w + wd.w * x0.w + wd.z * x1.w + wd.y * x2.w + wd.x * x3.w;

    float4 o;
    o.x = wmma::__float_to_tf32(__fdividef(acc.x, 1.f + __expf(-acc.x)));
    o.y = wmma::__float_to_tf32(__fdividef(acc.y, 1.f + __expf(-acc.y)));
    o.z = wmma::__float_to_tf32(__fdividef(acc.z, 1.f + __expf(-acc.z)));
    o.w = wmma::__float_to_tf32(__fdividef(acc.w, 1.f + __expf(-acc.w)));
    *(float4*)&g_xc[(size_t)row * DI + d] = o;
}

// ===========================================================================
// Parallel selective scan (3 passes), unchanged from R8.
// ===========================================================================
__global__ __launch_bounds__(128) void scan_part(
    const float* __restrict__ A_log_l,
    const float* __restrict__ Wdt_l, const float* __restrict__ bdt_l)
{
    __shared__ __align__(16) float s_dt[2][SCH][32];
    __shared__ __align__(16) float s_x [2][SCH][32];
    __shared__ __align__(16) float s_db[2][SCH][52];
    __shared__ float s_wdt[16][33];

    const int bx  = blockIdx.x;
    const int b   = bx / (16 * GG);
    const int rem = bx % (16 * GG);
    const int g   = rem >> 4;
    const int dg  = rem & 15;
    const int d0  = dg * 32;
    const int tid = threadIdx.x;
    const int q   = tid & 3;
    const int dl  = tid >> 2;
    const int d   = d0 + dl;

    const int tl  = tid >> 3;
    const int seg = tid & 7;

    const int r0 = tid / 12,         c0 = tid % 12;
    const int r1 = (tid + 128) / 12, c1 = (tid + 128) % 12;
    const bool ld1 = (tid < 64);

    for (int i = tid; i < 16 * 32; i += 128)
        s_wdt[i >> 5][i & 31] = Wdt_l[(i >> 5) * DI + d0 + (i & 31)];
    float bdt4[4];
#pragma unroll
    for (int j = 0; j < 4; j++)
        bdt4[j] = bdt_l[d0 + seg * 4 + j];

    float a[4];
#pragma unroll
    for (int j = 0; j < 4; j++)
        a[j] = -__expf(A_log_l[d * NST + q * 4 + j]);

    const size_t rb = (size_t)b * TT + (size_t)g * TG;

    float h0 = 0.f, h1 = 0.f, h2 = 0.f, h3 = 0.f;
    float sdt = 0.f;

    auto computeDt = [&](int bf) {
        float a0 = bdt4[0], a1 = bdt4[1], a2 = bdt4[2], a3 = bdt4[3];
#pragma unroll
        for (int r = 0; r < 16; r++) {
            float dbv = s_db[bf][tl][r];
            a0 += dbv * s_wdt[r][seg * 4 + 0];
            a1 += dbv * s_wdt[r][seg * 4 + 1];
            a2 += dbv * s_wdt[r][seg * 4 + 2];
            a3 += dbv * s_wdt[r][seg * 4 + 3];
        }
        s_dt[bf][tl][seg * 4 + 0] = (a0 > 20.f) ? a0 : log1pf(__expf(a0));
        s_dt[bf][tl][seg * 4 + 1] = (a1 > 20.f) ? a1 : log1pf(__expf(a1));
        s_dt[bf][tl][seg * 4 + 2] = (a2 > 20.f) ? a2 : log1pf(__expf(a2));
        s_dt[bf][tl][seg * 4 + 3] = (a3 > 20.f) ? a3 : log1pf(__expf(a3));
    };

    {
        size_t row = rb + tl;
        *(float4*)&s_x [0][tl][seg * 4] = *(const float4*)&g_xc[row * DI + d0 + seg * 4];
        *(float4*)&s_db[0][r0][c0 * 4]  = *(const float4*)&g_dbc[(rb + r0) * DBCN + c0 * 4];
        if (ld1)
            *(float4*)&s_db[0][r1][c1 * 4] = *(const float4*)&g_dbc[(rb + r1) * DBCN + c1 * 4];
    }
    __syncthreads();
    computeDt(0);
    __syncthreads();

    int buf = 0;
    const int NC = TG / SCH;
    for (int c = 0; c < NC; c++) {
        float4 vx, vdb0, vdb1;
        const bool more = (c + 1 < NC);
        if (more) {
            size_t cro = rb + (size_t)(c + 1) * SCH;
            vx   = *(const float4*)&g_xc[(cro + tl) * DI + d0 + seg * 4];
            vdb0 = *(const float4*)&g_dbc[(cro + r0) * DBCN + c0 * 4];
            if (ld1) vdb1 = *(const float4*)&g_dbc[(cro + r1) * DBCN + c1 * 4];
        }

#pragma unroll
        for (int it = 0; it < SCH; it++) {
            float dt  = s_dt[buf][it][dl];
            float x   = s_x [buf][it][dl];
            float4 Bv = *(const float4*)&s_db[buf][it][RR + q * 4];

            float dtx = dt * x;
            h0 = __expf(dt * a[0]) * h0 + dtx * Bv.x;
            h1 = __expf(dt * a[1]) * h1 + dtx * Bv.y;
            h2 = __expf(dt * a[2]) * h2 + dtx * Bv.z;
            h3 = __expf(dt * a[3]) * h3 + dtx * Bv.w;
            sdt += dt;
        }

        if (more) {
            *(float4*)&s_x [buf ^ 1][tl][seg * 4] = vx;
            *(float4*)&s_db[buf ^ 1][r0][c0 * 4]  = vdb0;
            if (ld1)
                *(float4*)&s_db[buf ^ 1][r1][c1 * 4] = vdb1;
            __syncthreads();
            computeDt(buf ^ 1);
            __syncthreads();
        }
        buf ^= 1;
    }

    const size_t base = ((size_t)(b * 16 + dg) * GG + g) * 512;
    g_hend[base + (q * 4 + 0) * 32 + dl] = h0;
    g_hend[base + (q * 4 + 1) * 32 + dl] = h1;
    g_hend[base + (q * 4 + 2) * 32 + dl] = h2;
    g_hend[base + (q * 4 + 3) * 32 + dl] = h3;
    if (q == 0)
        g_sdt[(size_t)(b * 16 + dg) * GG * 32 + (size_t)g * 32 + dl] = sdt;
}

__global__ __launch_bounds__(128) void scan_combine(const float* __restrict__ A_log_l)
{
    const int bx  = blockIdx.x;
    const int dg  = bx & 15;
    const int tid = threadIdx.x;
    const int q   = tid & 3;
    const int dl  = tid >> 2;
    const int d   = dg * 32 + dl;

    float a[4];
#pragma unroll
    for (int j = 0; j < 4; j++)
        a[j] = -__expf(A_log_l[d * NST + q * 4 + j]);

    float H[4] = {0.f, 0.f, 0.f, 0.f};
#pragma unroll
    for (int g = 0; g < GG; g++) {
        const size_t base = ((size_t)bx * GG + g) * 512;
#pragma unroll
        for (int j = 0; j < 4; j++)
            g_hin[base + (q * 4 + j) * 32 + dl] = H[j];
        float S = g_sdt[(size_t)bx * GG * 32 + (size_t)g * 32 + dl];
#pragma unroll
        for (int j = 0; j < 4; j++)
            H[j] = __expf(a[j] * S) * H[j] + g_hend[base + (q * 4 + j) * 32 + dl];
    }
}

__global__ __launch_bounds__(128) void scan_emit(
    const float* __restrict__ A_log_l, const float* __restrict__ Dp_l,
    const float* __restrict__ Wdt_l,   const float* __restrict__ bdt_l)
{
    __shared__ __align__(16) float s_dt[2][SCH][32];
    __shared__ __align__(16) float s_x [2][SCH][32];
    __shared__ __align__(16) float s_z [2][SCH][32];
    __shared__ __align__(16) float s_db[2][SCH][52];
    __shared__ float s_wdt[16][33];

    const int bx  = blockIdx.x;
    const int b   = bx / (16 * GG);
    const int rem = bx % (16 * GG);
    const int g   = rem >> 4;
    const int dg  = rem & 15;
    const int d0  = dg * 32;
    const int tid = threadIdx.x;
    const int q   = tid & 3;
    const int dl  = tid >> 2;
    const int d   = d0 + dl;

    const int tl  = tid >> 3;
    const int seg = tid & 7;

    const int r0 = tid / 12,         c0 = tid % 12;
    const int r1 = (tid + 128) / 12, c1 = (tid + 128) % 12;
    const bool ld1 = (tid < 64);

    for (int i = tid; i < 16 * 32; i += 128)
        s_wdt[i >> 5][i & 31] = Wdt_l[(i >> 5) * DI + d0 + (i & 31)];
    float bdt4[4];
#pragma unroll
    for (int j = 0; j < 4; j++)
        bdt4[j] = bdt_l[d0 + seg * 4 + j];

    float a[4];
#pragma unroll
    for (int j = 0; j < 4; j++)
        a[j] = -__expf(A_log_l[d * NST + q * 4 + j]);
    const float dp = Dp_l[d];

    const size_t rb = (size_t)b * TT + (size_t)g * TG;

    const size_t base = ((size_t)(b * 16 + dg) * GG + g) * 512;
    float h0 = g_hin[base + (q * 4 + 0) * 32 + dl];
    float h1 = g_hin[base + (q * 4 + 1) * 32 + dl];
    float h2 = g_hin[base + (q * 4 + 2) * 32 + dl];
    float h3 = g_hin[base + (q * 4 + 3) * 32 + dl];

    auto computeDt = [&](int bf) {
        float a0 = bdt4[0], a1 = bdt4[1], a2 = bdt4[2], a3 = bdt4[3];
#pragma unroll
        for (int r = 0; r < 16; r++) {
            float dbv = s_db[bf][tl][r];
            a0 += dbv * s_wdt[r][seg * 4 + 0];
            a1 += dbv * s_wdt[r][seg * 4 + 1];
            a2 += dbv * s_wdt[r][seg * 4 + 2];
            a3 += dbv * s_wdt[r][seg * 4 + 3];
        }
        s_dt[bf][tl][seg * 4 + 0] = (a0 > 20.f) ? a0 : log1pf(__expf(a0));
        s_dt[bf][tl][seg * 4 + 1] = (a1 > 20.f) ? a1 : log1pf(__expf(a1));
        s_dt[bf][tl][seg * 4 + 2] = (a2 > 20.f) ? a2 : log1pf(__expf(a2));
        s_dt[bf][tl][seg * 4 + 3] = (a3 > 20.f) ? a3 : log1pf(__expf(a3));
    };

    {
        size_t row = rb + tl;
        *(float4*)&s_x [0][tl][seg * 4] = *(const float4*)&g_xc[row * DI + d0 + seg * 4];
        *(float4*)&s_z [0][tl][seg * 4] = *(const float4*)&g_xz[row * (2 * DI) + DI + d0 + seg * 4];
        *(float4*)&s_db[0][r0][c0 * 4]  = *(const float4*)&g_dbc[(rb + r0) * DBCN + c0 * 4];
        if (ld1)
            *(float4*)&s_db[0][r1][c1 * 4] = *(const float4*)&g_dbc[(rb + r1) * DBCN + c1 * 4];
    }
    __syncthreads();
    computeDt(0);
    __syncthreads();

    int buf = 0;
    const int NC = TG / SCH;
    for (int c = 0; c < NC; c++) {
        float4 vx, vz, vdb0, vdb1;
        const bool more = (c + 1 < NC);
        if (more) {
            size_t cro = rb + (size_t)(c + 1) * SCH;
            size_t row = cro + tl;
            vx   = *(const float4*)&g_xc[row * DI + d0 + seg * 4];
            vz   = *(const float4*)&g_xz[row * (2 * DI) + DI + d0 + seg * 4];
            vdb0 = *(const float4*)&g_dbc[(cro + r0) * DBCN + c0 * 4];
            if (ld1) vdb1 = *(const float4*)&g_dbc[(cro + r1) * DBCN + c1 * 4];
        }

#pragma unroll
        for (int it = 0; it < SCH; it++) {
            float dt  = s_dt[buf][it][dl];
            float x   = s_x [buf][it][dl];
            float4 Bv = *(const float4*)&s_db[buf][it][RR + q * 4];
            float4 Cv = *(const float4*)&s_db[buf][it][RR + NST + q * 4];
            float z   = s_z [buf][it][dl];

            float dtx = dt * x;
            h0 = __expf(dt * a[0]) * h0 + dtx * Bv.x;
            h1 = __expf(dt * a[1]) * h1 + dtx * Bv.y;
            h2 = __expf(dt * a[2]) * h2 + dtx * Bv.z;
            h3 = __expf(dt * a[3]) * h3 + dtx * Bv.w;

            float pv = h0 * Cv.x + h1 * Cv.y + h2 * Cv.z + h3 * Cv.w;
            pv += __shfl_xor_sync(0xffffffffu, pv, 1);
            pv += __shfl_xor_sync(0xffffffffu, pv, 2);

            if (q == 0) {
                float sz = __fdividef(z, 1.f + __expf(-z));
                size_t row = rb + (size_t)c * SCH + it;
                g_y[row * DI + d] = wmma::__float_to_tf32((pv + dp * x) * sz);
            }
        }

        if (more) {
            *(float4*)&s_x [buf ^ 1][tl][seg * 4] = vx;
            *(float4*)&s_z [buf ^ 1][tl][seg * 4] = vz;
            *(float4*)&s_db[buf ^ 1][r0][c0 * 4]  = vdb0;
            if (ld1)
                *(float4*)&s_db[buf ^ 1][r1][c1 * 4] = vdb1;
            __syncthreads();
            computeDt(buf ^ 1);
            __syncthreads();
        }
        buf ^= 1;
    }
}

// ---------------------------------------------------------------------------
// Mean over T (two-stage) + out-projection
// ---------------------------------------------------------------------------
__global__ void mean_part()
{
    int b = blockIdx.x >> 5;
    int c = blockIdx.x & 31;
    int col = threadIdx.x;

    const float* hp = g_h + ((size_t)b * TT + (size_t)c * 64) * DM + col;
    float s = 0.f;
#pragma unroll 8
    for (int t = 0; t < 64; t++)
        s += hp[(size_t)t * DM];
    g_part[(b * 32 + c) * DM + col] = s;
}

__global__ void mean_proj2(const float* __restrict__ Wop,
                           const float* __restrict__ bop,
                           float* __restrict__ out)
{
    __shared__ float hm[DM];
    int b = blockIdx.x;
    int c = threadIdx.x;

    float s = 0.f;
#pragma unroll
    for (int i = 0; i < 32; i++)
        s += g_part[(b * 32 + i) * DM + c];
    hm[c] = s * (1.f / (float)TT);
    __syncthreads();

    if (c < DOUT) {
        float acc = bop[c];
#pragma unroll 4
        for (int k = 0; k < DM; k++)
            acc += hm[k] * Wop[k * DOUT + c];
        out[b * DOUT + c] = acc;
    }
}

// ---------------------------------------------------------------------------
// Orchestration
// ---------------------------------------------------------------------------
static constexpr int SMEM_T(int BN)
{
    return 4 * (128 * 20 + 16 * (BN + 4)) * 4;
}

extern "C" void kernel_launch(void* const* d_in, const int* in_sizes, int n_in,
                              void* d_out, int out_size)
{
    const float* x        = (const float*)d_in[0];
    const float* W_in     = (const float*)d_in[1];
    const float* b_in     = (const float*)d_in[2];
    const float* Win      = (const float*)d_in[3];
    const float* bin_     = (const float*)d_in[4];
    const float* conv_w   = (const float*)d_in[5];
    const float* conv_b   = (const float*)d_in[6];
    const float* Wx       = (const float*)d_in[7];
    const float* Wdt      = (const float*)d_in[8];
    const float* bdt      = (const float*)d_in[9];
    const float* A_log    = (const float*)d_in[10];
    const float* Dp       = (const float*)d_in[11];
    const float* Wout     = (const float*)d_in[12];
    const float* W_op     = (const float*)d_in[13];
    const float* b_op     = (const float*)d_in[14];
    float* out = (float*)d_out;

    float *hbuf, *xzbuf, *xcbuf, *dbcbuf, *ybuf, *wt, *wtT, *xtf;
    cudaGetSymbolAddress((void**)&hbuf,   g_h);
    cudaGetSymbolAddress((void**)&xzbuf,  g_xz);
    cudaGetSymbolAddress((void**)&xcbuf,  g_xc);
    cudaGetSymbolAddress((void**)&dbcbuf, g_dbc);
    cudaGetSymbolAddress((void**)&ybuf,   g_y);
    cudaGetSymbolAddress((void**)&wt,     g_wt);
    cudaGetSymbolAddress((void**)&wtT,    g_wtT);
    cudaGetSymbolAddress((void**)&xtf,    g_xtf);

    constexpr int SM48 = SMEM_T(48);
    cudaFuncSetAttribute(tgemm<48, 8>, cudaFuncAttributeMaxDynamicSharedMemorySize, SM48);
    cudaFuncSetAttribute(mgemm,        cudaFuncAttributeMaxDynamicSharedMemorySize, MSMEM);

    // launch 1: truncate Wx + x
    {
        CvtJobs jobs;
        jobs.j[0] = { Wx, wt + WX_OFF, LAY * DI * DBCN };
        jobs.j[1] = { x,  xtf,         ROWS * DIN      };
        int total = jobs.j[0].n + jobs.j[1].n;
        tf32_cvt_multi<<<(total + 255) / 256, 256>>>(jobs, total);
    }
    // launch 2: transpose+truncate Win, Wout, W_in -> [N,K]
    {
        int total = LAY * 2 * DI * DM + LAY * DM * DI + DM * DIN;
        cvt_T<<<(total + 255) / 256, 256>>>(Win, Wout, W_in,
                                            wtT + WINT_OFF, wtT + WOUTT_OFF,
                                            wtT + WINPT_OFF);
    }

    // launch 3: in_proj (mma.sync)
    {
        dim3 g(DM / 128, ROWS / 128);
        mgemm<<<g, 256, MSMEM>>>(xtf, wtT + WINPT_OFF, b_in, hbuf,
                                 ROWS, DM, DIN, 1);
    }

    const int CONV_BLOCKS = (ROWS * (DI / 4) + 255) / 256;

    for (int l = 0; l < LAY; l++) {
        const float* WinT_l  = wtT + WINT_OFF  + (size_t)l * 2 * DI * DM;
        const float* WoutT_l = wtT + WOUTT_OFF + (size_t)l * DM * DI;
        const float* bin_l  = bin_   + (size_t)l * 2 * DI;
        const float* cw_l   = conv_w + (size_t)l * DI * 4;
        const float* cb_l   = conv_b + (size_t)l * DI;
        const float* Wx_l   = wt + WX_OFF + (size_t)l * DI * DBCN;
        const float* Wdt_l  = Wdt    + (size_t)l * RR * DI;
        const float* bdt_l  = bdt    + (size_t)l * DI;
        const float* Alog_l = A_log  + (size_t)l * DI * NST;
        const float* Dp_l   = Dp     + (size_t)l * DI;

        // launch 4 (l=0): xz = h @ Win + bin (mma.sync) -> profiled slot
        {
            dim3 g((2 * DI) / 128, ROWS / 128);
            mgemm<<<g, 256, MSMEM>>>(hbuf, WinT_l, bin_l, xzbuf,
                                     ROWS, 2 * DI, DM, 0);
        }
        // conv
        conv_silu_v4<<<CONV_BLOCKS, 256>>>(cw_l, cb_l);
        // dbc = xc @ Wx (wmma)
        {
            dim3 g(1, ROWS / 128);
            tgemm<48, 8><<<g, 256, SM48>>>(xcbuf, Wx_l, nullptr, dbcbuf,
                                           ROWS, DBCN, DI, 0);
        }
        // parallel scan
        scan_part   <<<BB * 16 * GG, 128>>>(Alog_l, Wdt_l, bdt_l);
        scan_combine<<<BB * 16,      128>>>(Alog_l);
        scan_emit   <<<BB * 16 * GG, 128>>>(Alog_l, Dp_l, Wdt_l, bdt_l);
        // h = y @ Wout (mma.sync)
        {
            dim3 g(DM / 128, ROWS / 128);
            mgemm<<<g, 256, MSMEM>>>(ybuf, WoutT_l, nullptr, hbuf,
                                     ROWS, DM, DI, 1);
        }
    }

    mean_part<<<BB * 32, DM>>>();
    mean_proj2<<<BB, DM>>>(W_op, b_op, out);
}

// round 11
// speedup vs baseline: 2.2199x; 1.0034x over previous
#include <cuda_runtime.h>
#include <cstdint>
#include <math.h>
#include <mma.h>

using namespace nvcuda;

// Problem constants
#define BB   8
#define TT   2048
#define ROWS (BB * TT)      // 16384
#define DIN  64
#define DM   256
#define DI   512
#define NST  16
#define RR   16
#define DOUT 128
#define DBCN 48             // R + 2N
#define LAY  2
// parallel scan split
#define GG   8
#define TG   (TT / GG)
#define SCH  16

// ---------------------------------------------------------------------------
// Scratch (static device globals)
// ---------------------------------------------------------------------------
__device__ float g_h   [ROWS * DM];
__device__ float g_xz  [ROWS * 2 * DI];
__device__ float g_xc  [ROWS * DI];
__device__ float g_dbc [ROWS * DBCN];
__device__ float g_y   [ROWS * DI];
__device__ float g_part[BB * 32 * DM];
__device__ float g_hend[BB * 16 * GG * 512];
__device__ float g_hin [BB * 16 * GG * 512];
__device__ float g_sdt [BB * 16 * GG * 32];
// tf32 weights (wmma dbc path, original [K,N] layout)
#define WX_OFF    0
#define WT_TOTAL  (WX_OFF + LAY * DI * DBCN)
__device__ float g_wt [WT_TOTAL];
// tf32 TRANSPOSED weights [N,K] for mma.sync path
#define WINT_OFF  0                           // [LAY][2*DI][DM]
#define WOUTT_OFF (LAY * 2 * DI * DM)         // [LAY][DM][DI]
#define WINPT_OFF (WOUTT_OFF + LAY * DM * DI) // [DM][DIN]
#define WTT_TOTAL (WINPT_OFF + DM * DIN)
__device__ float g_wtT[WTT_TOTAL];
__device__ float g_xtf[ROWS * DIN];

// ---------------------------------------------------------------------------
// tf32 truncation kernels
// ---------------------------------------------------------------------------
struct CvtJob  { const float* src; float* dst; int n; };
struct CvtJobs { CvtJob j[2]; };

__global__ void tf32_cvt_multi(CvtJobs jobs, int total)
{
    int i = blockIdx.x * blockDim.x + threadIdx.x;
    if (i >= total) return;
#pragma unroll
    for (int k = 0; k < 2; k++) {
        if (i < jobs.j[k].n) {
            jobs.j[k].dst[i] = wmma::__float_to_tf32(jobs.j[k].src[i]);
            return;
        }
        i -= jobs.j[k].n;
    }
}

// transpose+truncate Win, Wout, W_in into [N,K] layout for mma B operand
__global__ void cvt_T(const float* __restrict__ Win, const float* __restrict__ Wout,
                      const float* __restrict__ W_in,
                      float* __restrict__ WinT, float* __restrict__ WoutT,
                      float* __restrict__ WinpT)
{
    int i = blockIdx.x * blockDim.x + threadIdx.x;
    if (i < LAY * 2 * DI * DM) {
        int l = i / (2 * DI * DM);
        int r = i % (2 * DI * DM);
        int n = r / DM;
        int k = r % DM;
        WinT[i] = wmma::__float_to_tf32(Win[(size_t)l * 2 * DI * DM + (size_t)k * (2 * DI) + n]);
        return;
    }
    i -= LAY * 2 * DI * DM;
    if (i < LAY * DM * DI) {
        int l = i / (DM * DI);
        int r = i % (DM * DI);
        int n = r / DI;
        int k = r % DI;
        WoutT[i] = wmma::__float_to_tf32(Wout[(size_t)l * DM * DI + (size_t)k * DM + n]);
        return;
    }
    i -= LAY * DM * DI;
    if (i < DM * DIN) {
        int n = i / DIN;
        int k = i % DIN;
        WinpT[i] = wmma::__float_to_tf32(W_in[(size_t)k * DM + n]);
    }
}

// ---------------------------------------------------------------------------
// cp.async helpers
// ---------------------------------------------------------------------------
__device__ __forceinline__ void cp16(unsigned int smem_addr, const float* gptr)
{
    asm volatile("cp.async.cg.shared.global [%0], [%1], 16;\n"
                 :: "r"(smem_addr), "l"(gptr));
}
__device__ __forceinline__ void cp_commit()
{
    asm volatile("cp.async.commit_group;\n");
}
template<int N>
__device__ __forceinline__ void cp_wait()
{
    asm volatile("cp.async.wait_group %0;\n" :: "n"(N));
}
__device__ __forceinline__ unsigned int smem_u32_of(const void* p)
{
    unsigned int a;
    asm("{ .reg .u64 t; cvta.to.shared.u64 t, %1; cvt.u32.u64 %0, t; }"
        : "=r"(a) : "l"(p));
    return a;
}

// ---------------------------------------------------------------------------
// mma.sync helpers (tf32 m16n8k8, ldmatrix fragment loads)
// ---------------------------------------------------------------------------
__device__ __forceinline__ void ldsm_x4(uint32_t& r0, uint32_t& r1,
                                        uint32_t& r2, uint32_t& r3,
                                        unsigned int addr)
{
    asm volatile("ldmatrix.sync.aligned.m8n8.x4.shared.b16 {%0,%1,%2,%3}, [%4];"
                 : "=r"(r0), "=r"(r1), "=r"(r2), "=r"(r3) : "r"(addr));
}
__device__ __forceinline__ void mma_tf32(float* d, const uint32_t* a, const uint32_t* b)
{
    asm volatile("mma.sync.aligned.m16n8k8.row.col.f32.tf32.tf32.f32 "
                 "{%0,%1,%2,%3}, {%4,%5,%6,%7}, {%8,%9}, {%0,%1,%2,%3};"
                 : "+f"(d[0]), "+f"(d[1]), "+f"(d[2]), "+f"(d[3])
                 : "r"(a[0]), "r"(a[1]), "r"(a[2]), "r"(a[3]),
                   "r"(b[0]), "r"(b[1]));
}

// ---------------------------------------------------------------------------
// mma.sync TF32 GEMM: C[M,N] = A[M,K] @ Bt[N,K]^T (+ bias).
// CTA tile 128x128, BK=16, 4-stage cp.async, 8 warps (4m x 2n), warp 32x64.
// Fragment loads via ldmatrix.x4.b16, row stride 80B (conflict-free).
// Requires M%128==0, N%128==0, K%16==0, K>=48.
// ---------------------------------------------------------------------------
#define MST   4
#define MROWB 80
#define MASZ  (128 * MROWB)          // 10240 B per operand per stage
#define MSMEM (2 * MST * MASZ)       // 81920 B

__global__ __launch_bounds__(256, 2) void mgemm(
    const float* __restrict__ A, const float* __restrict__ Bt,
    const float* __restrict__ bias, float* __restrict__ C,
    int M, int N, int K, int trunc_out)
{
    extern __shared__ char msm[];
    char* As = msm;
    char* Bs = msm + MST * MASZ;

    const int tid  = threadIdx.x;
    const int lane = tid & 31;
    const int wid  = tid >> 5;
    const int wm   = wid & 3;           // 0..3 -> rows wm*32
    const int wn   = wid >> 2;          // 0..1 -> cols wn*64
    const int brow = blockIdx.y * 128;
    const int bcol = blockIdx.x * 128;

    float acc[2][8][4];
#pragma unroll
    for (int i = 0; i < 2; i++)
#pragma unroll
        for (int j = 0; j < 8; j++)
#pragma unroll
            for (int q = 0; q < 4; q++) acc[i][j][q] = 0.f;

    const unsigned int asmb = smem_u32_of(As);
    const unsigned int bsmb = smem_u32_of(Bs);

    const int lr  = tid >> 2;            // 0..63
    const int lcB = (tid & 3) * 16;      // byte col 0/16/32/48

    auto loadStage = [&](int st, int k0) {
        unsigned int ab = asmb + st * MASZ;
        unsigned int bb = bsmb + st * MASZ;
#pragma unroll
        for (int u = 0; u < 2; u++) {
            int r = lr + u * 64;
            cp16(ab + r * MROWB + lcB, &A [(size_t)(brow + r) * K + k0 + (lcB >> 2)]);
            cp16(bb + r * MROWB + lcB, &Bt[(size_t)(bcol + r) * K + k0 + (lcB >> 2)]);
        }
    };

    const int ktiles = K / 16;
#pragma unroll
    for (int s = 0; s < MST - 1; s++) {
        if (s < ktiles) loadStage(s, s * 16);
        cp_commit();
    }

    const int mq = lane >> 3;            // matrix quad 0..3
    const int r8 = lane & 7;

    for (int kt = 0; kt < ktiles; kt++) {
        cp_wait<MST - 2>();
        __syncthreads();

        const int st = kt % MST;
        const unsigned int ab = asmb + st * MASZ;
        const unsigned int bb = bsmb + st * MASZ;
#pragma unroll
        for (int s = 0; s < 2; s++) {    // two k8 slices per ktile
            uint32_t af[2][4];
#pragma unroll
            for (int i = 0; i < 2; i++) {
                unsigned int row  = wm * 32 + i * 16 + (mq & 1) * 8 + r8;
                unsigned int addr = ab + row * MROWB + s * 32 + (mq >> 1) * 16;
                ldsm_x4(af[i][0], af[i][1], af[i][2], af[i][3], addr);
            }
            uint32_t bf[8][2];
#pragma unroll
            for (int jp = 0; jp < 4; jp++) {
                unsigned int row  = wn * 64 + jp * 16 + (mq >> 1) * 8 + r8;
                unsigned int addr = bb + row * MROWB + s * 32 + (mq & 1) * 16;
                uint32_t t0, t1, t2, t3;
                ldsm_x4(t0, t1, t2, t3, addr);
                bf[jp * 2 + 0][0] = t0;  bf[jp * 2 + 0][1] = t1;
                bf[jp * 2 + 1][0] = t2;  bf[jp * 2 + 1][1] = t3;
            }
#pragma unroll
            for (int i = 0; i < 2; i++)
#pragma unroll
                for (int j = 0; j < 8; j++)
                    mma_tf32(acc[i][j], af[i], bf[j]);
        }

        const int nf = kt + MST - 1;
        if (nf < ktiles) loadStage(nf % MST, nf * 16);
        cp_commit();
    }
    cp_wait<0>();

    // epilogue: accum layout c0,c1 = (g, 2c..2c+1), c2,c3 = (g+8, same)
    const int g  = lane >> 2;
    const int c2 = (lane & 3) * 2;
#pragma unroll
    for (int i = 0; i < 2; i++) {
#pragma unroll
        for (int j = 0; j < 8; j++) {
            int gr = brow + wm * 32 + i * 16 + g;
            int gc = bcol + wn * 64 + j * 8 + c2;
            float b0 = bias ? bias[gc]     : 0.f;
            float b1 = bias ? bias[gc + 1] : 0.f;
            float v0 = acc[i][j][0] + b0, v1 = acc[i][j][1] + b1;
            float v2 = acc[i][j][2] + b0, v3 = acc[i][j][3] + b1;
            if (trunc_out) {
                v0 = wmma::__float_to_tf32(v0);
                v1 = wmma::__float_to_tf32(v1);
                v2 = wmma::__float_to_tf32(v2);
                v3 = wmma::__float_to_tf32(v3);
            }
            *(float2*)&C[(size_t)gr * N + gc]       = make_float2(v0, v1);
            *(float2*)&C[(size_t)(gr + 8) * N + gc] = make_float2(v2, v3);
        }
    }
}

// ---------------------------------------------------------------------------
// wmma TF32 GEMM (kept for dbc), 4-stage cp.async pipeline.
// ---------------------------------------------------------------------------
template<int BN, int WM>
__global__ __launch_bounds__(256, 2) void tgemm(
    const float* __restrict__ A, const float* __restrict__ B,
    const float* __restrict__ bias, float* __restrict__ C,
    int M, int N, int K, int trunc_out)
{
    constexpr int BM = 128, BK = 16, STAGES = 4;
    constexpr int LDA = BK + 4;
    constexpr int LDB = BN + 4;
    constexpr int ASZ = BM * LDA;
    constexpr int BSZ = BK * LDB;
    constexpr int WNW = 8 / WM;
    constexpr int AM  = BM / (WM * 16);
    constexpr int NF  = BN / (WNW * 16);
    constexpr int NB4 = BN / 4;
    constexpr int BCH = BK * BN / 4;

    extern __shared__ float smem[];
    float* As = smem;
    float* Bs = smem + STAGES * ASZ;

    const int tid  = threadIdx.x;
    const int lane = tid & 31;
    const int wid  = tid >> 5;
    const int wm   = wid % WM;
    const int wn   = wid / WM;
    const int brow = blockIdx.y * BM;
    const int bcol = blockIdx.x * BN;

    wmma::fragment<wmma::accumulator, 16, 16, 8, float> acc[AM][NF];
#pragma unroll
    for (int i = 0; i < AM; i++)
#pragma unroll
        for (int j = 0; j < NF; j++)
            wmma::fill_fragment(acc[i][j], 0.f);

    const int ar0 = tid >> 2;
    const int ar1 = (tid + 256) >> 2;
    const int ac  = (tid & 3) * 4;

    auto loadStage = [&](int st, int k0) {
        unsigned int abase = (unsigned int)__cvta_generic_to_shared(As + st * ASZ);
        cp16(abase + (unsigned int)(ar0 * LDA + ac) * 4,
             &A[(size_t)(brow + ar0) * K + k0 + ac]);
        cp16(abase + (unsigned int)(ar1 * LDA + ac) * 4,
             &A[(size_t)(brow + ar1) * K + k0 + ac]);
        unsigned int bbase = (unsigned int)__cvta_generic_to_shared(Bs + st * BSZ);
#pragma unroll
        for (int u = 0; u < (BCH + 255) / 256; u++) {
            int i = tid + 256 * u;
            if ((BCH % 256 == 0) || (i < BCH)) {
                int r = i / NB4, c = (i % NB4) * 4;
                cp16(bbase + (unsigned int)(r * LDB + c) * 4,
                     &B[(size_t)(k0 + r) * N + bcol + c]);
            }
        }
    };

    const int ktiles = K / BK;

#pragma unroll
    for (int s = 0; s < STAGES - 1; s++) {
        if (s < ktiles) loadStage(s, s * BK);
        cp_commit();
    }

    for (int it = 0; it < ktiles; it++) {
        cp_wait<STAGES - 2>();
        __syncthreads();

        const int st = it % STAGES;
        const float* a0 = As + st * ASZ;
        const float* b0 = Bs + st * BSZ;
#pragma unroll
        for (int kk = 0; kk < BK; kk += 8) {
            wmma::fragment<wmma::matrix_a, 16, 16, 8, wmma::precision::tf32,
                           wmma::row_major> af[AM];
            wmma::fragment<wmma::matrix_b, 16, 16, 8, wmma::precision::tf32,
                           wmma::row_major> bf[NF];
#pragma unroll
            for (int i = 0; i < AM; i++)
                wmma::load_matrix_sync(af[i],
                    a0 + (wm * AM * 16 + i * 16) * LDA + kk, LDA);
#pragma unroll
            for (int j = 0; j < NF; j++)
                wmma::load_matrix_sync(bf[j],
                    b0 + kk * LDB + wn * NF * 16 + j * 16, LDB);
#pragma unroll
            for (int i = 0; i < AM; i++)
#pragma unroll
                for (int j = 0; j < NF; j++)
                    wmma::mma_sync(acc[i][j], af[i], bf[j], acc[i][j]);
        }

        const int nf = it + STAGES - 1;
        if (nf < ktiles) loadStage(nf % STAGES, nf * BK);
        cp_commit();
    }

    cp_wait<0>();
    __syncthreads();

    float* Ep = smem + wid * 256;
    const int er = lane >> 1;
    const int ec = (lane & 1) * 8;
#pragma unroll
    for (int i = 0; i < AM; i++) {
#pragma unroll
        for (int j = 0; j < NF; j++) {
            wmma::store_matrix_sync(Ep, acc[i][j], 16, wmma::mem_row_major);
            __syncwarp();
            int gr = brow + wm * AM * 16 + i * 16 + er;
            int gc = bcol + wn * NF * 16 + j * 16 + ec;
            float v[8];
#pragma unroll
            for (int q = 0; q < 8; q++) {
                float t = Ep[er * 16 + ec + q] + (bias ? bias[gc + q] : 0.f);
                v[q] = trunc_out ? wmma::__float_to_tf32(t) : t;
            }
            *(float4*)&C[(size_t)gr * N + gc]     = make_float4(v[0], v[1], v[2], v[3]);
            *(float4*)&C[(size_t)gr * N + gc + 4] = make_float4(v[4], v[5], v[6], v[7]);
            __syncwarp();
        }
    }
}

// ---------------------------------------------------------------------------
// Depthwise causal conv (K=4) + SiLU, float4 over d.
// ---------------------------------------------------------------------------
__global__ void conv_silu_v4(const float* __restrict__ cw,
                             const float* __restrict__ cb)
{
    int idx = blockIdx.x * blockDim.x + threadIdx.x;
    if (idx >= ROWS * (DI / 4)) return;
    int dv  = idx & (DI / 4 - 1);
    int row = idx >> 7;
    int t   = row & (TT - 1);
    int d   = dv * 4;

    const float* xi = g_xz + (size_t)row * (2 * DI) + d;
    float4 x0 = *(const float4*)xi;
    float4 x1 = (t >= 1) ? *(const float4*)(xi - 2 * DI) : make_float4(0, 0, 0, 0);
    float4 x2 = (t >= 2) ? *(const float4*)(xi - 4 * DI) : make_float4(0, 0, 0, 0);
    float4 x3 = (t >= 3) ? *(const float4*)(xi - 6 * DI) : make_float4(0, 0, 0, 0);

    float4 wa = *(const float4*)&cw[(d + 0) * 4];
    float4 wb = *(const float4*)&cw[(d + 1) * 4];
    float4 wc = *(const float4*)&cw[(d + 2) * 4];
    float4 wd = *(const float4*)&cw[(d + 3) * 4];
    float4 bc = *(const float4*)&cb[d];

    float4 acc;
    acc.x = bc.x + wa.w * x0.x + wa.z * x1.x + wa.y * x2.x + wa.x * x3.x;
    acc.y = bc.y + wb.w * x0.y + wb.z * x1.y + wb.y * x2.y + wb.x * x3.y;
    acc.z = bc.z + wc.w * x0.z + wc.z * x1.z + wc.y * x2.z + wc.x * x3.z;
    acc.w = bc.w + wd.w * x0.w + wd.z * x1.w + wd.y * x2.w + wd.x * x3.w;

    float4 o;
    o.x = wmma::__float_to_tf32(__fdividef(acc.x, 1.f + __expf(-acc.x)));
    o.y = wmma::__float_to_tf32(__fdividef(acc.y, 1.f + __expf(-acc.y)));
    o.z = wmma::__float_to_tf32(__fdividef(acc.z, 1.f + __expf(-acc.z)));
    o.w = wmma::__float_to_tf32(__fdividef(acc.w, 1.f + __expf(-acc.w)));
    *(float4*)&g_xc[(size_t)row * DI + d] = o;
}

// ===========================================================================
// Parallel selective scan (3 passes), unchanged from R8.
// ===========================================================================
__global__ __launch_bounds__(128) void scan_part(
    const float* __restrict__ A_log_l,
    const float* __restrict__ Wdt_l, const float* __restrict__ bdt_l)
{
    __shared__ __align__(16) float s_dt[2][SCH][32];
    __shared__ __align__(16) float s_x [2][SCH][32];
    __shared__ __align__(16) float s_db[2][SCH][52];
    __shared__ float s_wdt[16][33];

    const int bx  = blockIdx.x;
    const int b   = bx / (16 * GG);
    const int rem = bx % (16 * GG);
    const int g   = rem >> 4;
    const int dg  = rem & 15;
    const int d0  = dg * 32;
    const int tid = threadIdx.x;
    const int q   = tid & 3;
    const int dl  = tid >> 2;
    const int d   = d0 + dl;

    const int tl  = tid >> 3;
    const int seg = tid & 7;

    const int r0 = tid / 12,         c0 = tid % 12;
    const int r1 = (tid + 128) / 12, c1 = (tid + 128) % 12;
    const bool ld1 = (tid < 64);

    for (int i = tid; i < 16 * 32; i += 128)
        s_wdt[i >> 5][i & 31] = Wdt_l[(i >> 5) * DI + d0 + (i & 31)];
    float bdt4[4];
#pragma unroll
    for (int j = 0; j < 4; j++)
        bdt4[j] = bdt_l[d0 + seg * 4 + j];

    float a[4];
#pragma unroll
    for (int j = 0; j < 4; j++)
        a[j] = -__expf(A_log_l[d * NST + q * 4 + j]);

    const size_t rb = (size_t)b * TT + (size_t)g * TG;

    float h0 = 0.f, h1 = 0.f, h2 = 0.f, h3 = 0.f;
    float sdt = 0.f;

    auto computeDt = [&](int bf) {
        float a0 = bdt4[0], a1 = bdt4[1], a2 = bdt4[2], a3 = bdt4[3];
#pragma unroll
        for (int r = 0; r < 16; r++) {
            float dbv = s_db[bf][tl][r];
            a0 += dbv * s_wdt[r][seg * 4 + 0];
            a1 += dbv * s_wdt[r][seg * 4 + 1];
            a2 += dbv * s_wdt[r][seg * 4 + 2];
            a3 += dbv * s_wdt[r][seg * 4 + 3];
        }
        s_dt[bf][tl][seg * 4 + 0] = (a0 > 20.f) ? a0 : log1pf(__expf(a0));
        s_dt[bf][tl][seg * 4 + 1] = (a1 > 20.f) ? a1 : log1pf(__expf(a1));
        s_dt[bf][tl][seg * 4 + 2] = (a2 > 20.f) ? a2 : log1pf(__expf(a2));
        s_dt[bf][tl][seg * 4 + 3] = (a3 > 20.f) ? a3 : log1pf(__expf(a3));
    };

    {
        size_t row = rb + tl;
        *(float4*)&s_x [0][tl][seg * 4] = *(const float4*)&g_xc[row * DI + d0 + seg * 4];
        *(float4*)&s_db[0][r0][c0 * 4]  = *(const float4*)&g_dbc[(rb + r0) * DBCN + c0 * 4];
        if (ld1)
            *(float4*)&s_db[0][r1][c1 * 4] = *(const float4*)&g_dbc[(rb + r1) * DBCN + c1 * 4];
    }
    __syncthreads();
    computeDt(0);
    __syncthreads();

    int buf = 0;
    const int NC = TG / SCH;
    for (int c = 0; c < NC; c++) {
        float4 vx, vdb0, vdb1;
        const bool more = (c + 1 < NC);
        if (more) {
            size_t cro = rb + (size_t)(c + 1) * SCH;
            vx   = *(const float4*)&g_xc[(cro + tl) * DI + d0 + seg * 4];
            vdb0 = *(const float4*)&g_dbc[(cro + r0) * DBCN + c0 * 4];
            if (ld1) vdb1 = *(const float4*)&g_dbc[(cro + r1) * DBCN + c1 * 4];
        }

#pragma unroll
        for (int it = 0; it < SCH; it++) {
            float dt  = s_dt[buf][it][dl];
            float x   = s_x [buf][it][dl];
            float4 Bv = *(const float4*)&s_db[buf][it][RR + q * 4];

            float dtx = dt * x;
            h0 = __expf(dt * a[0]) * h0 + dtx * Bv.x;
            h1 = __expf(dt * a[1]) * h1 + dtx * Bv.y;
            h2 = __expf(dt * a[2]) * h2 + dtx * Bv.z;
            h3 = __expf(dt * a[3]) * h3 + dtx * Bv.w;
            sdt += dt;
        }

        if (more) {
            *(float4*)&s_x [buf ^ 1][tl][seg * 4] = vx;
            *(float4*)&s_db[buf ^ 1][r0][c0 * 4]  = vdb0;
            if (ld1)
                *(float4*)&s_db[buf ^ 1][r1][c1 * 4] = vdb1;
            __syncthreads();
            computeDt(buf ^ 1);
            __syncthreads();
        }
        buf ^= 1;
    }

    const size_t base = ((size_t)(b * 16 + dg) * GG + g) * 512;
    g_hend[base + (q * 4 + 0) * 32 + dl] = h0;
    g_hend[base + (q * 4 + 1) * 32 + dl] = h1;
    g_hend[base + (q * 4 + 2) * 32 + dl] = h2;
    g_hend[base + (q * 4 + 3) * 32 + dl] = h3;
    if (q == 0)
        g_sdt[(size_t)(b * 16 + dg) * GG * 32 + (size_t)g * 32 + dl] = sdt;
}

__global__ __launch_bounds__(128) void scan_combine(const float* __restrict__ A_log_l)
{
    const int bx  = blockIdx.x;
    const int dg  = bx & 15;
    const int tid = threadIdx.x;
    const int q   = tid & 3;
    const int dl  = tid >> 2;
    const int d   = dg * 32 + dl;

    float a[4];
#pragma unroll
    for (int j = 0; j < 4; j++)
        a[j] = -__expf(A_log_l[d * NST + q * 4 + j]);

    float H[4] = {0.f, 0.f, 0.f, 0.f};
#pragma unroll
    for (int g = 0; g < GG; g++) {
        const size_t base = ((size_t)bx * GG + g) * 512;
#pragma unroll
        for (int j = 0; j < 4; j++)
            g_hin[base + (q * 4 + j) * 32 + dl] = H[j];
        float S = g_sdt[(size_t)bx * GG * 32 + (size_t)g * 32 + dl];
#pragma unroll
        for (int j = 0; j < 4; j++)
            H[j] = __expf(a[j] * S) * H[j] + g_hend[base + (q * 4 + j) * 32 + dl];
    }
}

__global__ __launch_bounds__(128) void scan_emit(
    const float* __restrict__ A_log_l, const float* __restrict__ Dp_l,
    const float* __restrict__ Wdt_l,   const float* __restrict__ bdt_l)
{
    __shared__ __align__(16) float s_dt[2][SCH][32];
    __shared__ __align__(16) float s_x [2][SCH][32];
    __shared__ __align__(16) float s_z [2][SCH][32];
    __shared__ __align__(16) float s_db[2][SCH][52];
    __shared__ float s_wdt[16][33];

    const int bx  = blockIdx.x;
    const int b   = bx / (16 * GG);
    const int rem = bx % (16 * GG);
    const int g   = rem >> 4;
    const int dg  = rem & 15;
    const int d0  = dg * 32;
    const int tid = threadIdx.x;
    const int q   = tid & 3;
    const int dl  = tid >> 2;
    const int d   = d0 + dl;

    const int tl  = tid >> 3;
    const int seg = tid & 7;

    const int r0 = tid / 12,         c0 = tid % 12;
    const int r1 = (tid + 128) / 12, c1 = (tid + 128) % 12;
    const bool ld1 = (tid < 64);

    for (int i = tid; i < 16 * 32; i += 128)
        s_wdt[i >> 5][i & 31] = Wdt_l[(i >> 5) * DI + d0 + (i & 31)];
    float bdt4[4];
#pragma unroll
    for (int j = 0; j < 4; j++)
        bdt4[j] = bdt_l[d0 + seg * 4 + j];

    float a[4];
#pragma unroll
    for (int j = 0; j < 4; j++)
        a[j] = -__expf(A_log_l[d * NST + q * 4 + j]);
    const float dp = Dp_l[d];

    const size_t rb = (size_t)b * TT + (size_t)g * TG;

    const size_t base = ((size_t)(b * 16 + dg) * GG + g) * 512;
    float h0 = g_hin[base + (q * 4 + 0) * 32 + dl];
    float h1 = g_hin[base + (q * 4 + 1) * 32 + dl];
    float h2 = g_hin[base + (q * 4 + 2) * 32 + dl];
    float h3 = g_hin[base + (q * 4 + 3) * 32 + dl];

    auto computeDt = [&](int bf) {
        float a0 = bdt4[0], a1 = bdt4[1], a2 = bdt4[2], a3 = bdt4[3];
#pragma unroll
        for (int r = 0; r < 16; r++) {
            float dbv = s_db[bf][tl][r];
            a0 += dbv * s_wdt[r][seg * 4 + 0];
            a1 += dbv * s_wdt[r][seg * 4 + 1];
            a2 += dbv * s_wdt[r][seg * 4 + 2];
            a3 += dbv * s_wdt[r][seg * 4 + 3];
        }
        s_dt[bf][tl][seg * 4 + 0] = (a0 > 20.f) ? a0 : log1pf(__expf(a0));
        s_dt[bf][tl][seg * 4 + 1] = (a1 > 20.f) ? a1 : log1pf(__expf(a1));
        s_dt[bf][tl][seg * 4 + 2] = (a2 > 20.f) ? a2 : log1pf(__expf(a2));
        s_dt[bf][tl][seg * 4 + 3] = (a3 > 20.f) ? a3 : log1pf(__expf(a3));
    };

    {
        size_t row = rb + tl;
        *(float4*)&s_x [0][tl][seg * 4] = *(const float4*)&g_xc[row * DI + d0 + seg * 4];
        *(float4*)&s_z [0][tl][seg * 4] = *(const float4*)&g_xz[row * (2 * DI) + DI + d0 + seg * 4];
        *(float4*)&s_db[0][r0][c0 * 4]  = *(const float4*)&g_dbc[(rb + r0) * DBCN + c0 * 4];
        if (ld1)
            *(float4*)&s_db[0][r1][c1 * 4] = *(const float4*)&g_dbc[(rb + r1) * DBCN + c1 * 4];
    }
    __syncthreads();
    computeDt(0);
    __syncthreads();

    int buf = 0;
    const int NC = TG / SCH;
    for (int c = 0; c < NC; c++) {
        float4 vx, vz, vdb0, vdb1;
        const bool more = (c + 1 < NC);
        if (more) {
            size_t cro = rb + (size_t)(c + 1) * SCH;
            size_t row = cro + tl;
            vx   = *(const float4*)&g_xc[row * DI + d0 + seg * 4];
            vz   = *(const float4*)&g_xz[row * (2 * DI) + DI + d0 + seg * 4];
            vdb0 = *(const float4*)&g_dbc[(cro + r0) * DBCN + c0 * 4];
            if (ld1) vdb1 = *(const float4*)&g_dbc[(cro + r1) * DBCN + c1 * 4];
        }

#pragma unroll
        for (int it = 0; it < SCH; it++) {
            float dt  = s_dt[buf][it][dl];
            float x   = s_x [buf][it][dl];
            float4 Bv = *(const float4*)&s_db[buf][it][RR + q * 4];
            float4 Cv = *(const float4*)&s_db[buf][it][RR + NST + q * 4];
            float z   = s_z [buf][it][dl];

            float dtx = dt * x;
            h0 = __expf(dt * a[0]) * h0 + dtx * Bv.x;
            h1 = __expf(dt * a[1]) * h1 + dtx * Bv.y;
            h2 = __expf(dt * a[2]) * h2 + dtx * Bv.z;
            h3 = __expf(dt * a[3]) * h3 + dtx * Bv.w;

            float pv = h0 * Cv.x + h1 * Cv.y + h2 * Cv.z + h3 * Cv.w;
            pv += __shfl_xor_sync(0xffffffffu, pv, 1);
            pv += __shfl_xor_sync(0xffffffffu, pv, 2);

            if (q == 0) {
                float sz = __fdividef(z, 1.f + __expf(-z));
                size_t row = rb + (size_t)c * SCH + it;
                g_y[row * DI + d] = wmma::__float_to_tf32((pv + dp * x) * sz);
            }
        }

        if (more) {
            *(float4*)&s_x [buf ^ 1][tl][seg * 4] = vx;
            *(float4*)&s_z [buf ^ 1][tl][seg * 4] = vz;
            *(float4*)&s_db[buf ^ 1][r0][c0 * 4]  = vdb0;
            if (ld1)
                *(float4*)&s_db[buf ^ 1][r1][c1 * 4] = vdb1;
            __syncthreads();
            computeDt(buf ^ 1);
            __syncthreads();
        }
        buf ^= 1;
    }
}

// ---------------------------------------------------------------------------
// Mean over T (two-stage) + out-projection
// ---------------------------------------------------------------------------
__global__ void mean_part()
{
    int b = blockIdx.x >> 5;
    int c = blockIdx.x & 31;
    int col = threadIdx.x;

    const float* hp = g_h + ((size_t)b * TT + (size_t)c * 64) * DM + col;
    float s = 0.f;
#pragma unroll 8
    for (int t = 0; t < 64; t++)
        s += hp[(size_t)t * DM];
    g_part[(b * 32 + c) * DM + col] = s;
}

__global__ void mean_proj2(const float* __restrict__ Wop,
                           const float* __restrict__ bop,
                           float* __restrict__ out)
{
    __shared__ float hm[DM];
    int b = blockIdx.x;
    int c = threadIdx.x;

    float s = 0.f;
#pragma unroll
    for (int i = 0; i < 32; i++)
        s += g_part[(b * 32 + i) * DM + c];
    hm[c] = s * (1.f / (float)TT);
    __syncthreads();

    if (c < DOUT) {
        float acc = bop[c];
#pragma unroll 4
        for (int k = 0; k < DM; k++)
            acc += hm[k] * Wop[k * DOUT + c];
        out[b * DOUT + c] = acc;
    }
}

// ---------------------------------------------------------------------------
// Orchestration
// ---------------------------------------------------------------------------
static constexpr int SMEM_T(int BN)
{
    return 4 * (128 * 20 + 16 * (BN + 4)) * 4;
}

extern "C" void kernel_launch(void* const* d_in, const int* in_sizes, int n_in,
                              void* d_out, int out_size)
{
    const float* x        = (const float*)d_in[0];
    const float* W_in     = (const float*)d_in[1];
    const float* b_in     = (const float*)d_in[2];
    const float* Win      = (const float*)d_in[3];
    const float* bin_     = (const float*)d_in[4];
    const float* conv_w   = (const float*)d_in[5];
    const float* conv_b   = (const float*)d_in[6];
    const float* Wx       = (const float*)d_in[7];
    const float* Wdt      = (const float*)d_in[8];
    const float* bdt      = (const float*)d_in[9];
    const float* A_log    = (const float*)d_in[10];
    const float* Dp       = (const float*)d_in[11];
    const float* Wout     = (const float*)d_in[12];
    const float* W_op     = (const float*)d_in[13];
    const float* b_op     = (const float*)d_in[14];
    float* out = (float*)d_out;

    float *hbuf, *xzbuf, *xcbuf, *dbcbuf, *ybuf, *wt, *wtT, *xtf;
    cudaGetSymbolAddress((void**)&hbuf,   g_h);
    cudaGetSymbolAddress((void**)&xzbuf,  g_xz);
    cudaGetSymbolAddress((void**)&xcbuf,  g_xc);
    cudaGetSymbolAddress((void**)&dbcbuf, g_dbc);
    cudaGetSymbolAddress((void**)&ybuf,   g_y);
    cudaGetSymbolAddress((void**)&wt,     g_wt);
    cudaGetSymbolAddress((void**)&wtT,    g_wtT);
    cudaGetSymbolAddress((void**)&xtf,    g_xtf);

    constexpr int SM48 = SMEM_T(48);
    cudaFuncSetAttribute(tgemm<48, 8>, cudaFuncAttributeMaxDynamicSharedMemorySize, SM48);
    cudaFuncSetAttribute(mgemm,        cudaFuncAttributeMaxDynamicSharedMemorySize, MSMEM);

    // launch 1: truncate Wx + x
    {
        CvtJobs jobs;
        jobs.j[0] = { Wx, wt + WX_OFF, LAY * DI * DBCN };
        jobs.j[1] = { x,  xtf,         ROWS * DIN      };
        int total = jobs.j[0].n + jobs.j[1].n;
        tf32_cvt_multi<<<(total + 255) / 256, 256>>>(jobs, total);
    }
    // launch 2: transpose+truncate Win, Wout, W_in -> [N,K]
    {
        int total = LAY * 2 * DI * DM + LAY * DM * DI + DM * DIN;
        cvt_T<<<(total + 255) / 256, 256>>>(Win, Wout, W_in,
                                            wtT + WINT_OFF, wtT + WOUTT_OFF,
                                            wtT + WINPT_OFF);
    }

    // launch 3: in_proj (mma.sync)
    {
        dim3 g(DM / 128, ROWS / 128);
        mgemm<<<g, 256, MSMEM>>>(xtf, wtT + WINPT_OFF, b_in, hbuf,
                                 ROWS, DM, DIN, 1);
    }

    const int CONV_BLOCKS = (ROWS * (DI / 4) + 255) / 256;

    for (int l = 0; l < LAY; l++) {
        const float* WinT_l  = wtT + WINT_OFF  + (size_t)l * 2 * DI * DM;
        const float* WoutT_l = wtT + WOUTT_OFF + (size_t)l * DM * DI;
        const float* bin_l  = bin_   + (size_t)l * 2 * DI;
        const float* cw_l   = conv_w + (size_t)l * DI * 4;
        const float* cb_l   = conv_b + (size_t)l * DI;
        const float* Wx_l   = wt + WX_OFF + (size_t)l * DI * DBCN;
        const float* Wdt_l  = Wdt    + (size_t)l * RR * DI;
        const float* bdt_l  = bdt    + (size_t)l * DI;
        const float* Alog_l = A_log  + (size_t)l * DI * NST;
        const float* Dp_l   = Dp     + (size_t)l * DI;

        // launch 4 (l=0): xz = h @ Win + bin (mma.sync) -> profiled slot
        {
            dim3 g((2 * DI) / 128, ROWS / 128);
            mgemm<<<g, 256, MSMEM>>>(hbuf, WinT_l, bin_l, xzbuf,
                                     ROWS, 2 * DI, DM, 0);
        }
        // conv
        conv_silu_v4<<<CONV_BLOCKS, 256>>>(cw_l, cb_l);
        // dbc = xc @ Wx (wmma)
        {
            dim3 g(1, ROWS / 128);
            tgemm<48, 8><<<g, 256, SM48>>>(xcbuf, Wx_l, nullptr, dbcbuf,
                                           ROWS, DBCN, DI, 0);
        }
        // parallel scan
        scan_part   <<<BB * 16 * GG, 128>>>(Alog_l, Wdt_l, bdt_l);
        scan_combine<<<BB * 16,      128>>>(Alog_l);
        scan_emit   <<<BB * 16 * GG, 128>>>(Alog_l, Dp_l, Wdt_l, bdt_l);
        // h = y @ Wout (mma.sync)
        {
            dim3 g(DM / 128, ROWS / 128);
            mgemm<<<g, 256, MSMEM>>>(ybuf, WoutT_l, nullptr, hbuf,
                                     ROWS, DM, DI, 1);
        }
    }

    mean_part<<<BB * 32, DM>>>();
    mean_proj2<<<BB, DM>>>(W_op, b_op, out);
}